// round 10
// baseline (speedup 1.0000x reference)
#include <cuda_runtime.h>
#include <cuda_bf16.h>
#include <cstdint>

#define B_ 8
#define F_ 128
#define M_ 256
#define N_ 1024
#define H_ 64
#define O_ 128
#define NPB 4
#define ROWB 272   // X row bytes: 128 hi + 128 lo + 16 pad

// ---------------- scratch (device globals; no allocations allowed) ----------
__device__ __align__(16) float d_cos[B_ * N_ * M_];   // [b][n][m]
__device__ __align__(16) float d_Ap [B_ * H_ * M_];   // [b][h][m]
__device__ float d_nt [B_ * M_];
__device__ float d_ns [B_ * N_];
__device__ float d_w0 [H_];
__device__ float d_b2v[H_], d_b3v[H_], d_bc1v[H_];
// ldmatrix-ready bf16 weight images: [k=128 rows][64 g]; rows 0-63 = hi(W), 64-127 = lo(W)
__device__ __align__(16) unsigned short d_W2img[128 * 64];
__device__ __align__(16) unsigned short d_W3img[128 * 64];
__device__ __align__(16) float d_Wc1t[H_ * H_];
__device__ __align__(16) float d_Wc2t[H_ * O_];
__device__ __align__(16) float d_p  [B_ * N_ * H_];

// ================= tensor-core helpers (sm_80/90 PTX, valid on sm_103) ======
__device__ __forceinline__ uint32_t smem_to_u32(const void* p) {
    uint32_t a;
    asm("{ .reg .u64 t; cvta.to.shared.u64 t, %1; cvt.u32.u64 %0, t; }" : "=r"(a) : "l"(p));
    return a;
}
__device__ __forceinline__ void ldsm_x4(uint32_t r[4], uint32_t addr) {
    asm volatile("ldmatrix.sync.aligned.m8n8.x4.shared.b16 {%0,%1,%2,%3}, [%4];"
                 : "=r"(r[0]), "=r"(r[1]), "=r"(r[2]), "=r"(r[3]) : "r"(addr));
}
__device__ __forceinline__ void ldsm_x4t(uint32_t r[4], uint32_t addr) {
    asm volatile("ldmatrix.sync.aligned.m8n8.x4.trans.shared.b16 {%0,%1,%2,%3}, [%4];"
                 : "=r"(r[0]), "=r"(r[1]), "=r"(r[2]), "=r"(r[3]) : "r"(addr));
}
__device__ __forceinline__ void stsm_x4(uint32_t addr, const uint32_t r[4]) {
    asm volatile("stmatrix.sync.aligned.m8n8.x4.shared.b16 [%0], {%1,%2,%3,%4};"
                 :: "r"(addr), "r"(r[0]), "r"(r[1]), "r"(r[2]), "r"(r[3]) : "memory");
}
__device__ __forceinline__ void mma16816(float d[4], const uint32_t a[4],
                                         uint32_t b0, uint32_t b1) {
    asm volatile("mma.sync.aligned.m16n8k16.row.col.f32.bf16.bf16.f32 "
                 "{%0,%1,%2,%3}, {%4,%5,%6,%7}, {%8,%9}, {%0,%1,%2,%3};"
                 : "+f"(d[0]), "+f"(d[1]), "+f"(d[2]), "+f"(d[3])
                 : "r"(a[0]), "r"(a[1]), "r"(a[2]), "r"(a[3]), "r"(b0), "r"(b1));
}
// 2-warp pair barrier (warps mb and mb+4), named barrier id = mb+1
#define BARP(id) asm volatile("bar.sync %0, 64;" :: "r"(id) : "memory")

// fast hi/lo bf16 split: hi = bf16x2(y1,y0) (y0 in low half)
__device__ __forceinline__ uint32_t pack_split(float y0, float y1, uint32_t& lo) {
    uint32_t hi;
    asm("cvt.rn.bf16x2.f32 %0, %1, %2;" : "=r"(hi) : "f"(y1), "f"(y0));
    float y0h = __uint_as_float(hi << 16);
    float y1h = __uint_as_float(hi & 0xFFFF0000u);
    asm("cvt.rn.bf16x2.f32 %0, %1, %2;" : "=r"(lo) : "f"(y1 - y1h), "f"(y0 - y0h));
    return hi;
}

// ---------------- K0: fold BN into weights, emit ldmatrix bf16 images --------
__global__ void fold_kernel(const float* __restrict__ W1, const float* __restrict__ W2,
                            const float* __restrict__ W3, const float* __restrict__ Wc1,
                            const float* __restrict__ Wc2,
                            const float* __restrict__ g1, const float* __restrict__ v1,
                            const float* __restrict__ g2, const float* __restrict__ b2,
                            const float* __restrict__ m2, const float* __restrict__ v2,
                            const float* __restrict__ g3, const float* __restrict__ b3,
                            const float* __restrict__ m3, const float* __restrict__ v3,
                            const float* __restrict__ gc1, const float* __restrict__ bc1,
                            const float* __restrict__ mc1, const float* __restrict__ vc1) {
    __shared__ float a2s[H_], a3s[H_], ac1s[H_];
    int tid = threadIdx.x;
    if (tid < H_) {
        float A1 = g1[tid] * rsqrtf(v1[tid] + 1e-5f);
        d_w0[tid] = A1 * W1[tid * (F_ + 1)];
        float A2 = g2[tid] * rsqrtf(v2[tid] + 1e-5f);
        a2s[tid] = A2;  d_b2v[tid] = b2[tid] - A2 * m2[tid];
        float A3 = g3[tid] * rsqrtf(v3[tid] + 1e-5f);
        a3s[tid] = A3;  d_b3v[tid] = b3[tid] - A3 * m3[tid];
        float Ac = gc1[tid] * rsqrtf(vc1[tid] + 1e-5f);
        ac1s[tid] = Ac; d_bc1v[tid] = bc1[tid] - Ac * mc1[tid];
    }
    __syncthreads();
    // image rows k: [0,64)=hi(W), [64,128)=lo(W); h = k&63
    for (int i = tid; i < 128 * 64; i += 256) {
        int k = i >> 6, g = i & 63;
        int h = k & 63;
        float w2v = a2s[g] * W2[g * H_ + h];
        float w3v = a3s[g] * W3[g * H_ + h];
        __nv_bfloat16 h2 = __float2bfloat16(w2v);
        __nv_bfloat16 h3 = __float2bfloat16(w3v);
        __nv_bfloat16 v2b = (k < 64) ? h2 : __float2bfloat16(w2v - __bfloat162float(h2));
        __nv_bfloat16 v3b = (k < 64) ? h3 : __float2bfloat16(w3v - __bfloat162float(h3));
        uint32_t off = (uint32_t)k * 128u + ((((uint32_t)g >> 3) ^ ((uint32_t)k & 7u)) << 4)
                       + (((uint32_t)g & 7u) << 1);
        d_W2img[off >> 1] = __bfloat16_as_ushort(v2b);
        d_W3img[off >> 1] = __bfloat16_as_ushort(v3b);
    }
    for (int i = tid; i < H_ * H_; i += 256) {
        int k = i >> 6, g = i & 63;
        d_Wc1t[k * H_ + g] = ac1s[g] * Wc1[g * H_ + k];
    }
    for (int i = tid; i < H_ * O_; i += 256) {
        int h = i >> 7, o = i & 127;
        d_Wc2t[h * O_ + o] = Wc2[o * H_ + h];
    }
}

// ---------------- K1: A' = BN1-folded W1[:,1:] @ t ---------------------------
__global__ void ap_kernel(const float* __restrict__ t, const float* __restrict__ W1,
                          const float* __restrict__ g1, const float* __restrict__ b1,
                          const float* __restrict__ m1, const float* __restrict__ v1) {
    int bh = blockIdx.x;
    int b = bh >> 6, h = bh & 63;
    int m = threadIdx.x;
    __shared__ float w[F_];
    if (m < F_) w[m] = W1[h * (F_ + 1) + 1 + m];
    __syncthreads();
    const float* tp = t + (size_t)b * F_ * M_ + m;
    float acc = 0.f;
#pragma unroll 8
    for (int f = 0; f < F_; f++) acc = fmaf(w[f], tp[f * M_], acc);
    float A1 = g1[h] * rsqrtf(v1[h] + 1e-5f);
    float B1 = b1[h] - A1 * m1[h];
    d_Ap[bh * M_ + m] = fmaf(A1, acc, B1);
}

// ---------------- K2: column norms ------------------------------------------
__global__ void norm_kernel(const float* __restrict__ t, const float* __restrict__ s) {
    int idx = blockIdx.x * 256 + threadIdx.x;
    int b = idx / (M_ + N_);
    int r = idx - b * (M_ + N_);
    float acc = 0.f;
    if (r < M_) {
        const float* p = t + (size_t)b * F_ * M_ + r;
#pragma unroll 8
        for (int f = 0; f < F_; f++) { float v = p[f * M_]; acc = fmaf(v, v, acc); }
        d_nt[b * M_ + r] = sqrtf(acc);
    } else {
        int n = r - M_;
        const float* p = s + (size_t)b * F_ * N_ + n;
#pragma unroll 8
        for (int f = 0; f < F_; f++) { float v = p[f * N_]; acc = fmaf(v, v, acc); }
        d_ns[b * N_ + n] = sqrtf(acc);
    }
}

// ---------------- K3: cosine-similarity GEMM, stores [b][n][m] ---------------
__global__ void __launch_bounds__(256) cos_kernel(const float* __restrict__ t,
                                                  const float* __restrict__ s) {
    int b = blockIdx.z;
    int m0 = blockIdx.y * 64;
    int n0 = blockIdx.x * 64;
    __shared__ float ts[16][64];
    __shared__ float ss[16][64];
    int tid = threadIdx.x, ty = tid >> 4, tx = tid & 15;
    float acc[4][4] = {};
    const float* tb = t + (size_t)b * F_ * M_;
    const float* sb = s + (size_t)b * F_ * N_;
    for (int f0 = 0; f0 < F_; f0 += 16) {
        __syncthreads();
#pragma unroll
        for (int i = 0; i < 4; i++) {
            int e = tid + i * 256;
            int fr = e >> 6, cc = e & 63;
            ts[fr][cc] = tb[(f0 + fr) * M_ + m0 + cc];
            ss[fr][cc] = sb[(f0 + fr) * N_ + n0 + cc];
        }
        __syncthreads();
#pragma unroll
        for (int k = 0; k < 16; k++) {
            float4 av = *(const float4*)&ts[k][4 * ty];
            float4 bv = *(const float4*)&ss[k][4 * tx];
            float a0 = av.x, a1 = av.y, a2 = av.z, a3 = av.w;
            float b0 = bv.x, b1 = bv.y, b2 = bv.z, b3 = bv.w;
            acc[0][0] = fmaf(a0, b0, acc[0][0]); acc[0][1] = fmaf(a0, b1, acc[0][1]);
            acc[0][2] = fmaf(a0, b2, acc[0][2]); acc[0][3] = fmaf(a0, b3, acc[0][3]);
            acc[1][0] = fmaf(a1, b0, acc[1][0]); acc[1][1] = fmaf(a1, b1, acc[1][1]);
            acc[1][2] = fmaf(a1, b2, acc[1][2]); acc[1][3] = fmaf(a1, b3, acc[1][3]);
            acc[2][0] = fmaf(a2, b0, acc[2][0]); acc[2][1] = fmaf(a2, b1, acc[2][1]);
            acc[2][2] = fmaf(a2, b2, acc[2][2]); acc[2][3] = fmaf(a2, b3, acc[2][3]);
            acc[3][0] = fmaf(a3, b0, acc[3][0]); acc[3][1] = fmaf(a3, b1, acc[3][1]);
            acc[3][2] = fmaf(a3, b2, acc[3][2]); acc[3][3] = fmaf(a3, b3, acc[3][3]);
        }
    }
    float ntv[4], nsv[4];
#pragma unroll
    for (int r = 0; r < 4; r++) ntv[r] = d_nt[b * M_ + m0 + 4 * ty + r];
#pragma unroll
    for (int c = 0; c < 4; c++) nsv[c] = d_ns[b * N_ + n0 + 4 * tx + c];
#pragma unroll
    for (int c = 0; c < 4; c++) {
        int n = n0 + 4 * tx + c;
        float4 v;
        v.x = acc[0][c] / fmaxf(ntv[0] * nsv[c], 1e-8f);
        v.y = acc[1][c] / fmaxf(ntv[1] * nsv[c], 1e-8f);
        v.z = acc[2][c] / fmaxf(ntv[2] * nsv[c], 1e-8f);
        v.w = acc[3][c] / fmaxf(ntv[3] * nsv[c], 1e-8f);
        *(float4*)&d_cos[((size_t)b * N_ + n) * M_ + m0 + 4 * ty] = v;
    }
}

// ---------------- K4: fused MLP, R7 layout, gmem-Ap build, 3 blocks/SM -------
// SMEM map (bytes):
//  0       W2 image (16384)
//  16384   W3 image (16384)
//  32768   Xs [128 m][272B] split activations (34816)
//  67584   cos [4 nl][256 m] f32 (4096)
//  71680   red [4 nl][4 mb][64 g] f32 (4096)
//  75776   w0s (256) | 76032 b2s (256) | 76288 b3s (256)
#define XS_OFF   32768
#define COS_OFF  67584
#define RED_OFF  71680
#define W0_OFF   75776
#define B2_OFF   76032
#define B3_OFF   76288
#define MAIN_SMEM_BYTES 76544

// warp (gb,mb) computes [rows mb*32..+31] x [cols gb*32..+31], K=192
__device__ __forceinline__ void do_gemm(uint32_t xs_u32, uint32_t w_u32,
                                        int lane, int gb, int mb, float acc[2][4][4]) {
    uint32_t aaddr0 = xs_u32 + (uint32_t)((mb * 32 + (lane & 15)) * ROWB + ((lane >> 4) << 4));
    uint32_t aaddr1 = aaddr0 + 16 * ROWB;
    int kk = (lane & 7) + ((lane >> 3) & 1) * 8;
    int nc0 = gb * 4 + (lane >> 4);
    uint32_t baddr0 = w_u32 + (uint32_t)(kk * 128 + ((nc0 ^ (lane & 7)) << 4));
    uint32_t baddr1 = w_u32 + (uint32_t)(kk * 128 + (((nc0 + 2) ^ (lane & 7)) << 4));
    // K=192 in 12 k16-steps; A segs: hi, lo, hi(reuse); B segs: hi, hi(reuse), lo
#pragma unroll
    for (int k = 0; k < 12; k++) {
        int aoff = (k < 8 ? k : k - 8) * 32;
        int boff = (k < 4 ? k : k - 4) * 2048;
        uint32_t a0[4], a1[4], b0[4], b1[4];
        ldsm_x4 (a0, aaddr0 + aoff);
        ldsm_x4 (a1, aaddr1 + aoff);
        ldsm_x4t(b0, baddr0 + boff);
        ldsm_x4t(b1, baddr1 + boff);
        mma16816(acc[0][0], a0, b0[0], b0[1]); mma16816(acc[0][1], a0, b0[2], b0[3]);
        mma16816(acc[0][2], a0, b1[0], b1[1]); mma16816(acc[0][3], a0, b1[2], b1[3]);
        mma16816(acc[1][0], a1, b0[0], b0[1]); mma16816(acc[1][1], a1, b0[2], b0[3]);
        mma16816(acc[1][2], a1, b1[0], b1[1]); mma16816(acc[1][3], a1, b1[2], b1[3]);
    }
}

__global__ void __launch_bounds__(256, 3) main_kernel() {
    extern __shared__ char smem[];
    float* coss = (float*)(smem + COS_OFF);
    float* red  = (float*)(smem + RED_OFF);
    float* w0s  = (float*)(smem + W0_OFF);
    float* b2s  = (float*)(smem + B2_OFF);
    float* b3s  = (float*)(smem + B3_OFF);

    uint32_t sb32 = smem_to_u32(smem);
    uint32_t xs_u32 = sb32 + XS_OFF;

    int tid = threadIdx.x;
    int wid = tid >> 5, lane = tid & 31;
    int gb = wid >> 2, mb = wid & 3;
    int barid = mb + 1;
    int b = blockIdx.y;
    int n0 = blockIdx.x * NPB;

    // stage weights + cos + biases; init red
    {
        const uint4* sw2 = (const uint4*)d_W2img;
        const uint4* sw3 = (const uint4*)d_W3img;
        uint4* dw2 = (uint4*)smem;
        uint4* dw3 = (uint4*)(smem + 16384);
#pragma unroll
        for (int i = 0; i < 4; i++) {
            dw2[tid + i * 256] = sw2[tid + i * 256];
            dw3[tid + i * 256] = sw3[tid + i * 256];
        }
        const float4* cg = (const float4*)(d_cos + ((size_t)b * N_ + n0) * M_);
        ((float4*)coss)[tid] = cg[tid];
        if (tid < 64) {
            w0s[tid] = d_w0[tid];
            b2s[tid] = d_b2v[tid];
            b3s[tid] = d_b3v[tid];
        }
#pragma unroll
        for (int i = 0; i < 4; i++) red[tid + i * 256] = 0.f;
    }
    __syncthreads();

    for (int mt = 0; mt < 2; mt++) {
        // gmem base for this warp's build slice: rows mb*32+lane, h = gb*32..+31
        const float* apg = d_Ap + ((size_t)b * H_ + gb * 32) * M_ + mt * 128 + mb * 32 + lane;

        for (int nl = 0; nl < NPB; nl++) {
            // ---- build X1: warp (gb,mb) fills rows mb band, h-half gb ----
            {
                float cv = coss[nl * 256 + mt * 128 + mb * 32 + lane];
                char* row = smem + XS_OFF + (mb * 32 + lane) * ROWB + gb * 64;
#pragma unroll
                for (int oct = 0; oct < 4; oct++) {
                    uint4 hh, ll;
                    {
                        float a0 = __ldg(apg + (oct * 8 + 0) * M_);
                        float a1 = __ldg(apg + (oct * 8 + 1) * M_);
                        int hhx = gb * 32 + oct * 8;
                        float y0 = fmaxf(fmaf(w0s[hhx + 0], cv, a0), 0.f);
                        float y1 = fmaxf(fmaf(w0s[hhx + 1], cv, a1), 0.f);
                        hh.x = pack_split(y0, y1, ll.x);
                    }
                    {
                        float a0 = __ldg(apg + (oct * 8 + 2) * M_);
                        float a1 = __ldg(apg + (oct * 8 + 3) * M_);
                        int hhx = gb * 32 + oct * 8;
                        float y0 = fmaxf(fmaf(w0s[hhx + 2], cv, a0), 0.f);
                        float y1 = fmaxf(fmaf(w0s[hhx + 3], cv, a1), 0.f);
                        hh.y = pack_split(y0, y1, ll.y);
                    }
                    {
                        float a0 = __ldg(apg + (oct * 8 + 4) * M_);
                        float a1 = __ldg(apg + (oct * 8 + 5) * M_);
                        int hhx = gb * 32 + oct * 8;
                        float y0 = fmaxf(fmaf(w0s[hhx + 4], cv, a0), 0.f);
                        float y1 = fmaxf(fmaf(w0s[hhx + 5], cv, a1), 0.f);
                        hh.z = pack_split(y0, y1, ll.z);
                    }
                    {
                        float a0 = __ldg(apg + (oct * 8 + 6) * M_);
                        float a1 = __ldg(apg + (oct * 8 + 7) * M_);
                        int hhx = gb * 32 + oct * 8;
                        float y0 = fmaxf(fmaf(w0s[hhx + 6], cv, a0), 0.f);
                        float y1 = fmaxf(fmaf(w0s[hhx + 7], cv, a1), 0.f);
                        hh.w = pack_split(y0, y1, ll.w);
                    }
                    *(uint4*)(row + oct * 16)       = hh;
                    *(uint4*)(row + 128 + oct * 16) = ll;
                }
            }
            BARP(barid);

            // ---- GEMM1: W2f @ X1 ----
            float acc[2][4][4] = {};
            do_gemm(xs_u32, sb32, lane, gb, mb, acc);
            BARP(barid);   // pair done reading rows mb before overwrite

            // ---- epilogue 1: relu(+b2), split, stmatrix into own rows ----
            {
                int j = lane >> 3, r = lane & 7;
                int g0 = gb * 32 + 2 * (lane & 3);
                uint32_t adbase = xs_u32
                    + (uint32_t)((mb * 32 + (j & 1) * 8 + r) * ROWB + gb * 64 + (j >> 1) * 16);
#pragma unroll
                for (int i = 0; i < 2; i++) {
#pragma unroll
                    for (int tp = 0; tp < 2; tp++) {
                        int t0 = 2 * tp, t1 = t0 + 1;
                        float b00 = b2s[g0 + 8 * t0], b01 = b2s[g0 + 8 * t0 + 1];
                        float b10 = b2s[g0 + 8 * t1], b11 = b2s[g0 + 8 * t1 + 1];
                        uint32_t hh[4], ll[4];
                        hh[0] = pack_split(fmaxf(acc[i][t0][0] + b00, 0.f),
                                           fmaxf(acc[i][t0][1] + b01, 0.f), ll[0]);
                        hh[1] = pack_split(fmaxf(acc[i][t0][2] + b00, 0.f),
                                           fmaxf(acc[i][t0][3] + b01, 0.f), ll[1]);
                        hh[2] = pack_split(fmaxf(acc[i][t1][0] + b10, 0.f),
                                           fmaxf(acc[i][t1][1] + b11, 0.f), ll[2]);
                        hh[3] = pack_split(fmaxf(acc[i][t1][2] + b10, 0.f),
                                           fmaxf(acc[i][t1][3] + b11, 0.f), ll[3]);
                        uint32_t ad = adbase + (uint32_t)(i * 16 * ROWB + t0 * 16);
                        stsm_x4(ad, hh);
                        stsm_x4(ad + 128, ll);
                    }
                }
            }
            BARP(barid);

            // ---- GEMM2: W3f @ X2 ----
            float acc2[2][4][4] = {};
            do_gemm(xs_u32, sb32 + 16384, lane, gb, mb, acc2);

            // ---- epilogue 2: relu(+b3), max over m -> red RMW (race-free) ----
            {
                int g0 = gb * 32 + 2 * (lane & 3);
#pragma unroll
                for (int t = 0; t < 4; t++) {
#pragma unroll
                    for (int d = 0; d < 2; d++) {
                        int gg = g0 + d + 8 * t;
                        float v = fmaxf(fmaxf(acc2[0][t][d], acc2[0][t][2 + d]),
                                        fmaxf(acc2[1][t][d], acc2[1][t][2 + d]));
                        v = fmaxf(v + b3s[gg], 0.f);
                        v = fmaxf(v, __shfl_xor_sync(0xFFFFFFFFu, v, 4));
                        v = fmaxf(v, __shfl_xor_sync(0xFFFFFFFFu, v, 8));
                        v = fmaxf(v, __shfl_xor_sync(0xFFFFFFFFu, v, 16));
                        if (lane < 4) {
                            int ri = nl * 256 + mb * 64 + gg;
                            red[ri] = fmaxf(red[ri], v);
                        }
                    }
                }
            }
            BARP(barid);   // pair done reading rows mb before next build
        }
    }

    // final pooled reduce + write
    __syncthreads();
    {
        int nl = tid >> 6, h = tid & 63;
        const float* r = red + nl * 256;
        float v = fmaxf(fmaxf(r[h], r[64 + h]), fmaxf(r[128 + h], r[192 + h]));
        d_p[((size_t)b * N_ + n0 + nl) * H_ + h] = v;
    }
}

// ---------------- K5: head (Wc1 -> relu -> Wc2 + bc2) ------------------------
#define HEAD_SMEM_FLOATS 20608
__global__ void __launch_bounds__(256) head_kernel(const float* __restrict__ bc2,
                                                   float* __restrict__ out) {
    extern __shared__ float smf[];
    float* wc1s = smf;
    float* wc2s = smf + 4096;
    float* ps   = smf + 12288;
    float* cs   = smf + 16384;
    float* bc1s = smf + 20544;

    int b = blockIdx.y, n0 = blockIdx.x * 64;
    int tid = threadIdx.x;
#pragma unroll
    for (int i = 0; i < 16; i++) {
        int idx = tid + i * 256;
        wc1s[idx] = d_Wc1t[idx];
        ps[idx]   = d_p[((size_t)b * N_ + n0) * H_ + idx];
    }
#pragma unroll
    for (int i = 0; i < 32; i++) {
        int idx = tid + i * 256;
        wc2s[idx] = d_Wc2t[idx];
    }
    if (tid < 64) bc1s[tid] = d_bc1v[tid];
    __syncthreads();

#pragma unroll
    for (int i = 0; i < 16; i++) {
        int idx = tid + i * 256;
        int nn = idx >> 6, g = idx & 63;
        float acc = bc1s[g];
#pragma unroll 16
        for (int h = 0; h < 64; h++) acc = fmaf(wc1s[h * 64 + g], ps[nn * 64 + h], acc);
        cs[nn * 65 + g] = fmaxf(acc, 0.f);
    }
    __syncthreads();

#pragma unroll
    for (int i = 0; i < 32; i++) {
        int idx = tid + i * 256;
        int o = idx >> 6, nn = idx & 63;
        float acc = __ldg(bc2 + o);
#pragma unroll 16
        for (int h = 0; h < 64; h++) acc = fmaf(wc2s[h * 128 + o], cs[nn * 65 + h], acc);
        out[((size_t)b * O_ + o) * N_ + n0 + nn] = acc;
    }
}

// ---------------- launch ------------------------------------------------------
extern "C" void kernel_launch(void* const* d_in, const int* in_sizes, int n_in,
                              void* d_out, int out_size) {
    const float* t   = (const float*)d_in[0];
    const float* s   = (const float*)d_in[1];
    const float* W1  = (const float*)d_in[2];
    const float* W2  = (const float*)d_in[3];
    const float* W3  = (const float*)d_in[4];
    const float* Wc1 = (const float*)d_in[5];
    const float* Wc2 = (const float*)d_in[6];
    const float* bc2 = (const float*)d_in[7];
    const float* g1 = (const float*)d_in[8],  *b1 = (const float*)d_in[9];
    const float* m1 = (const float*)d_in[10], *v1 = (const float*)d_in[11];
    const float* g2 = (const float*)d_in[12], *b2 = (const float*)d_in[13];
    const float* m2 = (const float*)d_in[14], *v2 = (const float*)d_in[15];
    const float* g3 = (const float*)d_in[16], *b3 = (const float*)d_in[17];
    const float* m3 = (const float*)d_in[18], *v3 = (const float*)d_in[19];
    const float* gc1 = (const float*)d_in[20], *bc1 = (const float*)d_in[21];
    const float* mc1 = (const float*)d_in[22], *vc1 = (const float*)d_in[23];
    float* out = (float*)d_out;

    cudaFuncSetAttribute(main_kernel, cudaFuncAttributeMaxDynamicSharedMemorySize,
                         MAIN_SMEM_BYTES);
    cudaFuncSetAttribute(head_kernel, cudaFuncAttributeMaxDynamicSharedMemorySize,
                         HEAD_SMEM_FLOATS * 4);

    fold_kernel<<<1, 256>>>(W1, W2, W3, Wc1, Wc2, g1, v1,
                            g2, b2, m2, v2, g3, b3, m3, v3, gc1, bc1, mc1, vc1);
    ap_kernel<<<B_ * H_, 256>>>(t, W1, g1, b1, m1, v1);
    norm_kernel<<<(B_ * (M_ + N_)) / 256, 256>>>(t, s);
    cos_kernel<<<dim3(N_ / 64, M_ / 64, B_), 256>>>(t, s);
    main_kernel<<<dim3(N_ / NPB, B_), 256, MAIN_SMEM_BYTES>>>();
    head_kernel<<<dim3(N_ / 64, B_), 256, HEAD_SMEM_FLOATS * 4>>>(bc2, out);
}

// round 11
// speedup vs baseline: 1.3453x; 1.3453x over previous
#include <cuda_runtime.h>
#include <cuda_bf16.h>
#include <cstdint>

#define B_ 8
#define F_ 128
#define M_ 256
#define N_ 1024
#define H_ 64
#define O_ 128
#define NPB 8
#define ROWB 272   // X row bytes: 128 hi + 128 lo + 16 pad

// ---------------- scratch (device globals; no allocations allowed) ----------
__device__ __align__(16) float d_cos[B_ * N_ * M_];   // [b][n][m]
__device__ __align__(16) float d_Ap [B_ * H_ * M_];   // [b][h][m]
__device__ float d_nt [B_ * M_];
__device__ float d_ns [B_ * N_];
__device__ float d_w0 [H_];
__device__ float d_b2v[H_], d_b3v[H_], d_bc1v[H_];
// ldmatrix-ready bf16 weight images: [k=128 rows][64 g]; rows 0-63 = hi(W), 64-127 = lo(W)
__device__ __align__(16) unsigned short d_W2img[128 * 64];
__device__ __align__(16) unsigned short d_W3img[128 * 64];
__device__ __align__(16) float d_Wc1t[H_ * H_];
__device__ __align__(16) float d_Wc2t[H_ * O_];
__device__ __align__(16) float d_p  [B_ * N_ * H_];

// ================= tensor-core helpers (sm_80/90 PTX, valid on sm_103) ======
__device__ __forceinline__ uint32_t smem_to_u32(const void* p) {
    uint32_t a;
    asm("{ .reg .u64 t; cvta.to.shared.u64 t, %1; cvt.u32.u64 %0, t; }" : "=r"(a) : "l"(p));
    return a;
}
__device__ __forceinline__ void ldsm_x4(uint32_t r[4], uint32_t addr) {
    asm volatile("ldmatrix.sync.aligned.m8n8.x4.shared.b16 {%0,%1,%2,%3}, [%4];"
                 : "=r"(r[0]), "=r"(r[1]), "=r"(r[2]), "=r"(r[3]) : "r"(addr));
}
__device__ __forceinline__ void ldsm_x4t(uint32_t r[4], uint32_t addr) {
    asm volatile("ldmatrix.sync.aligned.m8n8.x4.trans.shared.b16 {%0,%1,%2,%3}, [%4];"
                 : "=r"(r[0]), "=r"(r[1]), "=r"(r[2]), "=r"(r[3]) : "r"(addr));
}
__device__ __forceinline__ void stsm_x4(uint32_t addr, const uint32_t r[4]) {
    asm volatile("stmatrix.sync.aligned.m8n8.x4.shared.b16 [%0], {%1,%2,%3,%4};"
                 :: "r"(addr), "r"(r[0]), "r"(r[1]), "r"(r[2]), "r"(r[3]) : "memory");
}
__device__ __forceinline__ void mma16816(float d[4], const uint32_t a[4],
                                         uint32_t b0, uint32_t b1) {
    asm volatile("mma.sync.aligned.m16n8k16.row.col.f32.bf16.bf16.f32 "
                 "{%0,%1,%2,%3}, {%4,%5,%6,%7}, {%8,%9}, {%0,%1,%2,%3};"
                 : "+f"(d[0]), "+f"(d[1]), "+f"(d[2]), "+f"(d[3])
                 : "r"(a[0]), "r"(a[1]), "r"(a[2]), "r"(a[3]), "r"(b0), "r"(b1));
}
// 2-warp pair barrier (warps mb and mb+4), named barrier id = mb+1
#define BARP(id) asm volatile("bar.sync %0, 64;" :: "r"(id) : "memory")

// fast hi/lo bf16 split: hi = bf16x2(y1,y0) (y0 in low half)
__device__ __forceinline__ uint32_t pack_split(float y0, float y1, uint32_t& lo) {
    uint32_t hi;
    asm("cvt.rn.bf16x2.f32 %0, %1, %2;" : "=r"(hi) : "f"(y1), "f"(y0));
    float y0h = __uint_as_float(hi << 16);
    float y1h = __uint_as_float(hi & 0xFFFF0000u);
    asm("cvt.rn.bf16x2.f32 %0, %1, %2;" : "=r"(lo) : "f"(y1 - y1h), "f"(y0 - y0h));
    return hi;
}

// ---------------- K0: fold BN into weights, emit ldmatrix bf16 images --------
__global__ void fold_kernel(const float* __restrict__ W1, const float* __restrict__ W2,
                            const float* __restrict__ W3, const float* __restrict__ Wc1,
                            const float* __restrict__ Wc2,
                            const float* __restrict__ g1, const float* __restrict__ v1,
                            const float* __restrict__ g2, const float* __restrict__ b2,
                            const float* __restrict__ m2, const float* __restrict__ v2,
                            const float* __restrict__ g3, const float* __restrict__ b3,
                            const float* __restrict__ m3, const float* __restrict__ v3,
                            const float* __restrict__ gc1, const float* __restrict__ bc1,
                            const float* __restrict__ mc1, const float* __restrict__ vc1) {
    __shared__ float a2s[H_], a3s[H_], ac1s[H_];
    int tid = threadIdx.x;
    if (tid < H_) {
        float A1 = g1[tid] * rsqrtf(v1[tid] + 1e-5f);
        d_w0[tid] = A1 * W1[tid * (F_ + 1)];
        float A2 = g2[tid] * rsqrtf(v2[tid] + 1e-5f);
        a2s[tid] = A2;  d_b2v[tid] = b2[tid] - A2 * m2[tid];
        float A3 = g3[tid] * rsqrtf(v3[tid] + 1e-5f);
        a3s[tid] = A3;  d_b3v[tid] = b3[tid] - A3 * m3[tid];
        float Ac = gc1[tid] * rsqrtf(vc1[tid] + 1e-5f);
        ac1s[tid] = Ac; d_bc1v[tid] = bc1[tid] - Ac * mc1[tid];
    }
    __syncthreads();
    // image rows k: [0,64)=hi(W), [64,128)=lo(W); h = k&63
    for (int i = tid; i < 128 * 64; i += 256) {
        int k = i >> 6, g = i & 63;
        int h = k & 63;
        float w2v = a2s[g] * W2[g * H_ + h];
        float w3v = a3s[g] * W3[g * H_ + h];
        __nv_bfloat16 h2 = __float2bfloat16(w2v);
        __nv_bfloat16 h3 = __float2bfloat16(w3v);
        __nv_bfloat16 v2b = (k < 64) ? h2 : __float2bfloat16(w2v - __bfloat162float(h2));
        __nv_bfloat16 v3b = (k < 64) ? h3 : __float2bfloat16(w3v - __bfloat162float(h3));
        uint32_t off = (uint32_t)k * 128u + ((((uint32_t)g >> 3) ^ ((uint32_t)k & 7u)) << 4)
                       + (((uint32_t)g & 7u) << 1);
        d_W2img[off >> 1] = __bfloat16_as_ushort(v2b);
        d_W3img[off >> 1] = __bfloat16_as_ushort(v3b);
    }
    for (int i = tid; i < H_ * H_; i += 256) {
        int k = i >> 6, g = i & 63;
        d_Wc1t[k * H_ + g] = ac1s[g] * Wc1[g * H_ + k];
    }
    for (int i = tid; i < H_ * O_; i += 256) {
        int h = i >> 7, o = i & 127;
        d_Wc2t[h * O_ + o] = Wc2[o * H_ + h];
    }
}

// ---------------- K1: A' = BN1-folded W1[:,1:] @ t ---------------------------
__global__ void ap_kernel(const float* __restrict__ t, const float* __restrict__ W1,
                          const float* __restrict__ g1, const float* __restrict__ b1,
                          const float* __restrict__ m1, const float* __restrict__ v1) {
    int bh = blockIdx.x;
    int b = bh >> 6, h = bh & 63;
    int m = threadIdx.x;
    __shared__ float w[F_];
    if (m < F_) w[m] = W1[h * (F_ + 1) + 1 + m];
    __syncthreads();
    const float* tp = t + (size_t)b * F_ * M_ + m;
    float acc = 0.f;
#pragma unroll 8
    for (int f = 0; f < F_; f++) acc = fmaf(w[f], tp[f * M_], acc);
    float A1 = g1[h] * rsqrtf(v1[h] + 1e-5f);
    float B1 = b1[h] - A1 * m1[h];
    d_Ap[bh * M_ + m] = fmaf(A1, acc, B1);
}

// ---------------- K2: column norms ------------------------------------------
__global__ void norm_kernel(const float* __restrict__ t, const float* __restrict__ s) {
    int idx = blockIdx.x * 256 + threadIdx.x;
    int b = idx / (M_ + N_);
    int r = idx - b * (M_ + N_);
    float acc = 0.f;
    if (r < M_) {
        const float* p = t + (size_t)b * F_ * M_ + r;
#pragma unroll 8
        for (int f = 0; f < F_; f++) { float v = p[f * M_]; acc = fmaf(v, v, acc); }
        d_nt[b * M_ + r] = sqrtf(acc);
    } else {
        int n = r - M_;
        const float* p = s + (size_t)b * F_ * N_ + n;
#pragma unroll 8
        for (int f = 0; f < F_; f++) { float v = p[f * N_]; acc = fmaf(v, v, acc); }
        d_ns[b * N_ + n] = sqrtf(acc);
    }
}

// ---------------- K3: cosine-similarity GEMM, stores [b][n][m] ---------------
__global__ void __launch_bounds__(256) cos_kernel(const float* __restrict__ t,
                                                  const float* __restrict__ s) {
    int b = blockIdx.z;
    int m0 = blockIdx.y * 64;
    int n0 = blockIdx.x * 64;
    __shared__ float ts[16][64];
    __shared__ float ss[16][64];
    int tid = threadIdx.x, ty = tid >> 4, tx = tid & 15;
    float acc[4][4] = {};
    const float* tb = t + (size_t)b * F_ * M_;
    const float* sb = s + (size_t)b * F_ * N_;
    for (int f0 = 0; f0 < F_; f0 += 16) {
        __syncthreads();
#pragma unroll
        for (int i = 0; i < 4; i++) {
            int e = tid + i * 256;
            int fr = e >> 6, cc = e & 63;
            ts[fr][cc] = tb[(f0 + fr) * M_ + m0 + cc];
            ss[fr][cc] = sb[(f0 + fr) * N_ + n0 + cc];
        }
        __syncthreads();
#pragma unroll
        for (int k = 0; k < 16; k++) {
            float4 av = *(const float4*)&ts[k][4 * ty];
            float4 bv = *(const float4*)&ss[k][4 * tx];
            float a0 = av.x, a1 = av.y, a2 = av.z, a3 = av.w;
            float b0 = bv.x, b1 = bv.y, b2 = bv.z, b3 = bv.w;
            acc[0][0] = fmaf(a0, b0, acc[0][0]); acc[0][1] = fmaf(a0, b1, acc[0][1]);
            acc[0][2] = fmaf(a0, b2, acc[0][2]); acc[0][3] = fmaf(a0, b3, acc[0][3]);
            acc[1][0] = fmaf(a1, b0, acc[1][0]); acc[1][1] = fmaf(a1, b1, acc[1][1]);
            acc[1][2] = fmaf(a1, b2, acc[1][2]); acc[1][3] = fmaf(a1, b3, acc[1][3]);
            acc[2][0] = fmaf(a2, b0, acc[2][0]); acc[2][1] = fmaf(a2, b1, acc[2][1]);
            acc[2][2] = fmaf(a2, b2, acc[2][2]); acc[2][3] = fmaf(a2, b3, acc[2][3]);
            acc[3][0] = fmaf(a3, b0, acc[3][0]); acc[3][1] = fmaf(a3, b1, acc[3][1]);
            acc[3][2] = fmaf(a3, b2, acc[3][2]); acc[3][3] = fmaf(a3, b3, acc[3][3]);
        }
    }
    float ntv[4], nsv[4];
#pragma unroll
    for (int r = 0; r < 4; r++) ntv[r] = d_nt[b * M_ + m0 + 4 * ty + r];
#pragma unroll
    for (int c = 0; c < 4; c++) nsv[c] = d_ns[b * N_ + n0 + 4 * tx + c];
#pragma unroll
    for (int c = 0; c < 4; c++) {
        int n = n0 + 4 * tx + c;
        float4 v;
        v.x = acc[0][c] / fmaxf(ntv[0] * nsv[c], 1e-8f);
        v.y = acc[1][c] / fmaxf(ntv[1] * nsv[c], 1e-8f);
        v.z = acc[2][c] / fmaxf(ntv[2] * nsv[c], 1e-8f);
        v.w = acc[3][c] / fmaxf(ntv[3] * nsv[c], 1e-8f);
        *(float4*)&d_cos[((size_t)b * N_ + n) * M_ + m0 + 4 * ty] = v;
    }
}

// ---------------- K4: fused MLP (R7 layout, NPB=8, cos from gmem) ------------
// SMEM map (bytes):
//  0       W2 image (16384)
//  16384   W3 image (16384)
//  32768   Xs [128 m][272B] split activations (34816)
//  67584   Ap tile [64 h][128 m] f32 (32768)
//  100352  red [8 nl][4 mb][64 g] f32 (8192)
//  108544  w0s (256) | 108800 b2s (256) | 109056 b3s (256)
#define XS_OFF   32768
#define AP_OFF   67584
#define RED_OFF  100352
#define W0_OFF   108544
#define B2_OFF   108800
#define B3_OFF   109056
#define MAIN_SMEM_BYTES 109312

// warp (gb,mb) computes [rows mb*32..+31] x [cols gb*32..+31], K=192
__device__ __forceinline__ void do_gemm(uint32_t xs_u32, uint32_t w_u32,
                                        int lane, int gb, int mb, float acc[2][4][4]) {
    uint32_t aaddr0 = xs_u32 + (uint32_t)((mb * 32 + (lane & 15)) * ROWB + ((lane >> 4) << 4));
    uint32_t aaddr1 = aaddr0 + 16 * ROWB;
    int kk = (lane & 7) + ((lane >> 3) & 1) * 8;
    int nc0 = gb * 4 + (lane >> 4);
    uint32_t baddr0 = w_u32 + (uint32_t)(kk * 128 + ((nc0 ^ (lane & 7)) << 4));
    uint32_t baddr1 = w_u32 + (uint32_t)(kk * 128 + (((nc0 + 2) ^ (lane & 7)) << 4));
    // K=192 in 12 k16-steps; A segs: hi, lo, hi(reuse); B segs: hi, hi(reuse), lo
#pragma unroll
    for (int k = 0; k < 12; k++) {
        int aoff = (k < 8 ? k : k - 8) * 32;
        int boff = (k < 4 ? k : k - 4) * 2048;
        uint32_t a0[4], a1[4], b0[4], b1[4];
        ldsm_x4 (a0, aaddr0 + aoff);
        ldsm_x4 (a1, aaddr1 + aoff);
        ldsm_x4t(b0, baddr0 + boff);
        ldsm_x4t(b1, baddr1 + boff);
        mma16816(acc[0][0], a0, b0[0], b0[1]); mma16816(acc[0][1], a0, b0[2], b0[3]);
        mma16816(acc[0][2], a0, b1[0], b1[1]); mma16816(acc[0][3], a0, b1[2], b1[3]);
        mma16816(acc[1][0], a1, b0[0], b0[1]); mma16816(acc[1][1], a1, b0[2], b0[3]);
        mma16816(acc[1][2], a1, b1[0], b1[1]); mma16816(acc[1][3], a1, b1[2], b1[3]);
    }
}

__global__ void __launch_bounds__(256, 2) main_kernel() {
    extern __shared__ char smem[];
    float* aps  = (float*)(smem + AP_OFF);
    float* red  = (float*)(smem + RED_OFF);
    float* w0s  = (float*)(smem + W0_OFF);
    float* b2s  = (float*)(smem + B2_OFF);
    float* b3s  = (float*)(smem + B3_OFF);

    uint32_t sb32 = smem_to_u32(smem);
    uint32_t xs_u32 = sb32 + XS_OFF;

    int tid = threadIdx.x;
    int wid = tid >> 5, lane = tid & 31;
    int gb = wid >> 2, mb = wid & 3;
    int barid = mb + 1;
    int b = blockIdx.y;
    int n0 = blockIdx.x * NPB;

    // stage weights + biases; init red
    {
        const uint4* sw2 = (const uint4*)d_W2img;
        const uint4* sw3 = (const uint4*)d_W3img;
        uint4* dw2 = (uint4*)smem;
        uint4* dw3 = (uint4*)(smem + 16384);
#pragma unroll
        for (int i = 0; i < 4; i++) {
            dw2[tid + i * 256] = sw2[tid + i * 256];
            dw3[tid + i * 256] = sw3[tid + i * 256];
        }
        if (tid < 64) {
            w0s[tid] = d_w0[tid];
            b2s[tid] = d_b2v[tid];
            b3s[tid] = d_b3v[tid];
        }
#pragma unroll
        for (int i = 0; i < 8; i++) red[tid + i * 256] = 0.f;
    }

    for (int mt = 0; mt < 2; mt++) {
        __syncthreads();   // all readers of aps/Xs from prev phase done
        {
            const float4* ag = (const float4*)d_Ap;
            float4* as = (float4*)aps;
#pragma unroll
            for (int i = 0; i < 8; i++) {
                int e = tid + i * 256;
                int h = e >> 5, q = e & 31;
                as[e] = ag[((size_t)b * 64 + h) * 64 + mt * 32 + q];
            }
        }
        __syncthreads();

        for (int nl = 0; nl < NPB; nl++) {
            // ---- build X1 (pair-closed rows): thread -> row m = tid&127 ----
            {
                int m = tid & 127;
                int hb = (tid >> 7) * 32;
                float cv = __ldg(d_cos + ((size_t)b * N_ + n0 + nl) * M_ + mt * 128 + m);
                char* row = smem + XS_OFF + m * ROWB;
#pragma unroll
                for (int cc = 0; cc < 4; cc++) {
                    int h0 = hb + 8 * cc;
                    float y0 = fmaxf(fmaf(w0s[h0 + 0], cv, aps[(h0 + 0) * 128 + m]), 0.f);
                    float y1 = fmaxf(fmaf(w0s[h0 + 1], cv, aps[(h0 + 1) * 128 + m]), 0.f);
                    float y2 = fmaxf(fmaf(w0s[h0 + 2], cv, aps[(h0 + 2) * 128 + m]), 0.f);
                    float y3 = fmaxf(fmaf(w0s[h0 + 3], cv, aps[(h0 + 3) * 128 + m]), 0.f);
                    float y4 = fmaxf(fmaf(w0s[h0 + 4], cv, aps[(h0 + 4) * 128 + m]), 0.f);
                    float y5 = fmaxf(fmaf(w0s[h0 + 5], cv, aps[(h0 + 5) * 128 + m]), 0.f);
                    float y6 = fmaxf(fmaf(w0s[h0 + 6], cv, aps[(h0 + 6) * 128 + m]), 0.f);
                    float y7 = fmaxf(fmaf(w0s[h0 + 7], cv, aps[(h0 + 7) * 128 + m]), 0.f);
                    uint4 hh, ll;
                    hh.x = pack_split(y0, y1, ll.x);
                    hh.y = pack_split(y2, y3, ll.y);
                    hh.z = pack_split(y4, y5, ll.z);
                    hh.w = pack_split(y6, y7, ll.w);
                    *(uint4*)(row + h0 * 2)       = hh;
                    *(uint4*)(row + 128 + h0 * 2) = ll;
                }
            }
            BARP(barid);

            // ---- GEMM1: W2f @ X1 ----
            float acc[2][4][4] = {};
            do_gemm(xs_u32, sb32, lane, gb, mb, acc);
            BARP(barid);   // pair done reading rows mb before overwrite

            // ---- epilogue 1: relu(+b2), split, stmatrix into own rows ----
            {
                int j = lane >> 3, r = lane & 7;
                int g0 = gb * 32 + 2 * (lane & 3);
                uint32_t adbase = xs_u32
                    + (uint32_t)((mb * 32 + (j & 1) * 8 + r) * ROWB + gb * 64 + (j >> 1) * 16);
#pragma unroll
                for (int i = 0; i < 2; i++) {
#pragma unroll
                    for (int tp = 0; tp < 2; tp++) {
                        int t0 = 2 * tp, t1 = t0 + 1;
                        float b00 = b2s[g0 + 8 * t0], b01 = b2s[g0 + 8 * t0 + 1];
                        float b10 = b2s[g0 + 8 * t1], b11 = b2s[g0 + 8 * t1 + 1];
                        uint32_t hh[4], ll[4];
                        hh[0] = pack_split(fmaxf(acc[i][t0][0] + b00, 0.f),
                                           fmaxf(acc[i][t0][1] + b01, 0.f), ll[0]);
                        hh[1] = pack_split(fmaxf(acc[i][t0][2] + b00, 0.f),
                                           fmaxf(acc[i][t0][3] + b01, 0.f), ll[1]);
                        hh[2] = pack_split(fmaxf(acc[i][t1][0] + b10, 0.f),
                                           fmaxf(acc[i][t1][1] + b11, 0.f), ll[2]);
                        hh[3] = pack_split(fmaxf(acc[i][t1][2] + b10, 0.f),
                                           fmaxf(acc[i][t1][3] + b11, 0.f), ll[3]);
                        uint32_t ad = adbase + (uint32_t)(i * 16 * ROWB + t0 * 16);
                        stsm_x4(ad, hh);
                        stsm_x4(ad + 128, ll);
                    }
                }
            }
            BARP(barid);

            // ---- GEMM2: W3f @ X2 ----
            float acc2[2][4][4] = {};
            do_gemm(xs_u32, sb32 + 16384, lane, gb, mb, acc2);

            // ---- epilogue 2: relu(+b3), max over m -> red RMW (race-free) ----
            {
                int g0 = gb * 32 + 2 * (lane & 3);
#pragma unroll
                for (int t = 0; t < 4; t++) {
#pragma unroll
                    for (int d = 0; d < 2; d++) {
                        int gg = g0 + d + 8 * t;
                        float v = fmaxf(fmaxf(acc2[0][t][d], acc2[0][t][2 + d]),
                                        fmaxf(acc2[1][t][d], acc2[1][t][2 + d]));
                        v = fmaxf(v + b3s[gg], 0.f);
                        v = fmaxf(v, __shfl_xor_sync(0xFFFFFFFFu, v, 4));
                        v = fmaxf(v, __shfl_xor_sync(0xFFFFFFFFu, v, 8));
                        v = fmaxf(v, __shfl_xor_sync(0xFFFFFFFFu, v, 16));
                        if (lane < 4) {
                            int ri = nl * 256 + mb * 64 + gg;
                            red[ri] = fmaxf(red[ri], v);
                        }
                    }
                }
            }
            BARP(barid);   // pair done reading rows mb before next build
        }
    }

    // final pooled reduce + write (8 nl x 64 h = 512 outputs, 2 per thread)
    __syncthreads();
#pragma unroll
    for (int i = 0; i < 2; i++) {
        int e = tid + i * 256;
        int nl = e >> 6, h = e & 63;
        const float* r = red + nl * 256;
        float v = fmaxf(fmaxf(r[h], r[64 + h]), fmaxf(r[128 + h], r[192 + h]));
        d_p[((size_t)b * N_ + n0 + nl) * H_ + h] = v;
    }
}

// ---------------- K5: head (Wc1 -> relu -> Wc2 + bc2) ------------------------
#define HEAD_SMEM_FLOATS 20608
__global__ void __launch_bounds__(256) head_kernel(const float* __restrict__ bc2,
                                                   float* __restrict__ out) {
    extern __shared__ float smf[];
    float* wc1s = smf;
    float* wc2s = smf + 4096;
    float* ps   = smf + 12288;
    float* cs   = smf + 16384;
    float* bc1s = smf + 20544;

    int b = blockIdx.y, n0 = blockIdx.x * 64;
    int tid = threadIdx.x;
#pragma unroll
    for (int i = 0; i < 16; i++) {
        int idx = tid + i * 256;
        wc1s[idx] = d_Wc1t[idx];
        ps[idx]   = d_p[((size_t)b * N_ + n0) * H_ + idx];
    }
#pragma unroll
    for (int i = 0; i < 32; i++) {
        int idx = tid + i * 256;
        wc2s[idx] = d_Wc2t[idx];
    }
    if (tid < 64) bc1s[tid] = d_bc1v[tid];
    __syncthreads();

#pragma unroll
    for (int i = 0; i < 16; i++) {
        int idx = tid + i * 256;
        int nn = idx >> 6, g = idx & 63;
        float acc = bc1s[g];
#pragma unroll 16
        for (int h = 0; h < 64; h++) acc = fmaf(wc1s[h * 64 + g], ps[nn * 64 + h], acc);
        cs[nn * 65 + g] = fmaxf(acc, 0.f);
    }
    __syncthreads();

#pragma unroll
    for (int i = 0; i < 32; i++) {
        int idx = tid + i * 256;
        int o = idx >> 6, nn = idx & 63;
        float acc = __ldg(bc2 + o);
#pragma unroll 16
        for (int h = 0; h < 64; h++) acc = fmaf(wc2s[h * 128 + o], cs[nn * 65 + h], acc);
        out[((size_t)b * O_ + o) * N_ + n0 + nn] = acc;
    }
}

// ---------------- launch ------------------------------------------------------
extern "C" void kernel_launch(void* const* d_in, const int* in_sizes, int n_in,
                              void* d_out, int out_size) {
    const float* t   = (const float*)d_in[0];
    const float* s   = (const float*)d_in[1];
    const float* W1  = (const float*)d_in[2];
    const float* W2  = (const float*)d_in[3];
    const float* W3  = (const float*)d_in[4];
    const float* Wc1 = (const float*)d_in[5];
    const float* Wc2 = (const float*)d_in[6];
    const float* bc2 = (const float*)d_in[7];
    const float* g1 = (const float*)d_in[8],  *b1 = (const float*)d_in[9];
    const float* m1 = (const float*)d_in[10], *v1 = (const float*)d_in[11];
    const float* g2 = (const float*)d_in[12], *b2 = (const float*)d_in[13];
    const float* m2 = (const float*)d_in[14], *v2 = (const float*)d_in[15];
    const float* g3 = (const float*)d_in[16], *b3 = (const float*)d_in[17];
    const float* m3 = (const float*)d_in[18], *v3 = (const float*)d_in[19];
    const float* gc1 = (const float*)d_in[20], *bc1 = (const float*)d_in[21];
    const float* mc1 = (const float*)d_in[22], *vc1 = (const float*)d_in[23];
    float* out = (float*)d_out;

    cudaFuncSetAttribute(main_kernel, cudaFuncAttributeMaxDynamicSharedMemorySize,
                         MAIN_SMEM_BYTES);
    cudaFuncSetAttribute(head_kernel, cudaFuncAttributeMaxDynamicSharedMemorySize,
                         HEAD_SMEM_FLOATS * 4);

    fold_kernel<<<1, 256>>>(W1, W2, W3, Wc1, Wc2, g1, v1,
                            g2, b2, m2, v2, g3, b3, m3, v3, gc1, bc1, mc1, vc1);
    ap_kernel<<<B_ * H_, 256>>>(t, W1, g1, b1, m1, v1);
    norm_kernel<<<(B_ * (M_ + N_)) / 256, 256>>>(t, s);
    cos_kernel<<<dim3(N_ / 64, M_ / 64, B_), 256>>>(t, s);
    main_kernel<<<dim3(N_ / NPB, B_), 256, MAIN_SMEM_BYTES>>>();
    head_kernel<<<dim3(N_ / 64, B_), 256, HEAD_SMEM_FLOATS * 4>>>(bc2, out);
}

// round 12
// speedup vs baseline: 1.5893x; 1.1814x over previous
#include <cuda_runtime.h>
#include <cuda_bf16.h>
#include <cuda_fp16.h>
#include <cstdint>

#define B_ 8
#define F_ 128
#define M_ 256
#define N_ 1024
#define H_ 64
#define O_ 128
#define NPB 8
#define ROWB 272   // X row bytes: 128 fp16 + 128 bf16 + 16 pad

// ---------------- scratch (device globals; no allocations allowed) ----------
__device__ __align__(16) float d_cos[B_ * N_ * M_];   // [b][n][m]
__device__ __align__(16) float d_Ap [B_ * H_ * M_];   // [b][h][m]
__device__ float d_w0 [H_];
__device__ float d_b2v[H_], d_b3v[H_], d_bc1v[H_];
// weight images [k=128 rows][64 g]: rows 0-63 = fp16(hi), rows 64-127 = bf16(lo)
__device__ __align__(16) unsigned short d_W2img[128 * 64];
__device__ __align__(16) unsigned short d_W3img[128 * 64];
__device__ __align__(16) float d_Wc1t[H_ * H_];
__device__ __align__(16) float d_Wc2t[H_ * O_];
__device__ __align__(16) float d_p  [B_ * N_ * H_];

// ================= tensor-core helpers (sm_80/90 PTX, valid on sm_103) ======
__device__ __forceinline__ uint32_t smem_to_u32(const void* p) {
    uint32_t a;
    asm("{ .reg .u64 t; cvta.to.shared.u64 t, %1; cvt.u32.u64 %0, t; }" : "=r"(a) : "l"(p));
    return a;
}
__device__ __forceinline__ void ldsm_x4(uint32_t r[4], uint32_t addr) {
    asm volatile("ldmatrix.sync.aligned.m8n8.x4.shared.b16 {%0,%1,%2,%3}, [%4];"
                 : "=r"(r[0]), "=r"(r[1]), "=r"(r[2]), "=r"(r[3]) : "r"(addr));
}
__device__ __forceinline__ void ldsm_x4t(uint32_t r[4], uint32_t addr) {
    asm volatile("ldmatrix.sync.aligned.m8n8.x4.trans.shared.b16 {%0,%1,%2,%3}, [%4];"
                 : "=r"(r[0]), "=r"(r[1]), "=r"(r[2]), "=r"(r[3]) : "r"(addr));
}
__device__ __forceinline__ void stsm_x4(uint32_t addr, const uint32_t r[4]) {
    asm volatile("stmatrix.sync.aligned.m8n8.x4.shared.b16 [%0], {%1,%2,%3,%4};"
                 :: "r"(addr), "r"(r[0]), "r"(r[1]), "r"(r[2]), "r"(r[3]) : "memory");
}
// bf16 mma
__device__ __forceinline__ void mma_bf16(float d[4], const uint32_t a[4],
                                         uint32_t b0, uint32_t b1) {
    asm volatile("mma.sync.aligned.m16n8k16.row.col.f32.bf16.bf16.f32 "
                 "{%0,%1,%2,%3}, {%4,%5,%6,%7}, {%8,%9}, {%0,%1,%2,%3};"
                 : "+f"(d[0]), "+f"(d[1]), "+f"(d[2]), "+f"(d[3])
                 : "r"(a[0]), "r"(a[1]), "r"(a[2]), "r"(a[3]), "r"(b0), "r"(b1));
}
// fp16 mma
__device__ __forceinline__ void mma_f16(float d[4], const uint32_t a[4],
                                        uint32_t b0, uint32_t b1) {
    asm volatile("mma.sync.aligned.m16n8k16.row.col.f32.f16.f16.f32 "
                 "{%0,%1,%2,%3}, {%4,%5,%6,%7}, {%8,%9}, {%0,%1,%2,%3};"
                 : "+f"(d[0]), "+f"(d[1]), "+f"(d[2]), "+f"(d[3])
                 : "r"(a[0]), "r"(a[1]), "r"(a[2]), "r"(a[3]), "r"(b0), "r"(b1));
}
// 2-warp pair barrier (warps mb and mb+4), named barrier id = mb+1
#define BARP(id) asm volatile("bar.sync %0, 64;" :: "r"(id) : "memory")

__device__ __forceinline__ uint32_t pack_f16(float y0, float y1) {
    __half2 h = __floats2half2_rn(y0, y1);      // y0 in low half
    return *reinterpret_cast<uint32_t*>(&h);
}
__device__ __forceinline__ uint32_t pack_bf16(float y0, float y1) {
    __nv_bfloat162 h = __floats2bfloat162_rn(y0, y1);  // y0 in low half
    return *reinterpret_cast<uint32_t*>(&h);
}

// ---------------- K0: fold BN into weights, emit fp16-hi / bf16-lo images ----
__global__ void fold_kernel(const float* __restrict__ W1, const float* __restrict__ W2,
                            const float* __restrict__ W3, const float* __restrict__ Wc1,
                            const float* __restrict__ Wc2,
                            const float* __restrict__ g1, const float* __restrict__ v1,
                            const float* __restrict__ g2, const float* __restrict__ b2,
                            const float* __restrict__ m2, const float* __restrict__ v2,
                            const float* __restrict__ g3, const float* __restrict__ b3,
                            const float* __restrict__ m3, const float* __restrict__ v3,
                            const float* __restrict__ gc1, const float* __restrict__ bc1,
                            const float* __restrict__ mc1, const float* __restrict__ vc1) {
    __shared__ float a2s[H_], a3s[H_], ac1s[H_];
    int tid = threadIdx.x;
    if (tid < H_) {
        float A1 = g1[tid] * rsqrtf(v1[tid] + 1e-5f);
        d_w0[tid] = A1 * W1[tid * (F_ + 1)];
        float A2 = g2[tid] * rsqrtf(v2[tid] + 1e-5f);
        a2s[tid] = A2;  d_b2v[tid] = b2[tid] - A2 * m2[tid];
        float A3 = g3[tid] * rsqrtf(v3[tid] + 1e-5f);
        a3s[tid] = A3;  d_b3v[tid] = b3[tid] - A3 * m3[tid];
        float Ac = gc1[tid] * rsqrtf(vc1[tid] + 1e-5f);
        ac1s[tid] = Ac; d_bc1v[tid] = bc1[tid] - Ac * mc1[tid];
    }
    __syncthreads();
    // image rows k: [0,64) = fp16(W), [64,128) = bf16(W - fp16(W)); h = k&63
    for (int i = tid; i < 128 * 64; i += 256) {
        int k = i >> 6, g = i & 63;
        int h = k & 63;
        float w2v = a2s[g] * W2[g * H_ + h];
        float w3v = a3s[g] * W3[g * H_ + h];
        unsigned short v2u, v3u;
        if (k < 64) {
            v2u = __half_as_ushort(__float2half_rn(w2v));
            v3u = __half_as_ushort(__float2half_rn(w3v));
        } else {
            float l2 = w2v - __half2float(__float2half_rn(w2v));
            float l3 = w3v - __half2float(__float2half_rn(w3v));
            v2u = __bfloat16_as_ushort(__float2bfloat16(l2));
            v3u = __bfloat16_as_ushort(__float2bfloat16(l3));
        }
        uint32_t off = (uint32_t)k * 128u + ((((uint32_t)g >> 3) ^ ((uint32_t)k & 7u)) << 4)
                       + (((uint32_t)g & 7u) << 1);
        d_W2img[off >> 1] = v2u;
        d_W3img[off >> 1] = v3u;
    }
    for (int i = tid; i < H_ * H_; i += 256) {
        int k = i >> 6, g = i & 63;
        d_Wc1t[k * H_ + g] = ac1s[g] * Wc1[g * H_ + k];
    }
    for (int i = tid; i < H_ * O_; i += 256) {
        int h = i >> 7, o = i & 127;
        d_Wc2t[h * O_ + o] = Wc2[o * H_ + h];
    }
}

// ---------------- K1: A' = BN1-folded W1[:,1:] @ t ---------------------------
__global__ void ap_kernel(const float* __restrict__ t, const float* __restrict__ W1,
                          const float* __restrict__ g1, const float* __restrict__ b1,
                          const float* __restrict__ m1, const float* __restrict__ v1) {
    int bh = blockIdx.x;
    int b = bh >> 6, h = bh & 63;
    int m = threadIdx.x;
    __shared__ float w[F_];
    if (m < F_) w[m] = W1[h * (F_ + 1) + 1 + m];
    __syncthreads();
    const float* tp = t + (size_t)b * F_ * M_ + m;
    float acc = 0.f;
#pragma unroll 8
    for (int f = 0; f < F_; f++) acc = fmaf(w[f], tp[f * M_], acc);
    float A1 = g1[h] * rsqrtf(v1[h] + 1e-5f);
    float B1 = b1[h] - A1 * m1[h];
    d_Ap[bh * M_ + m] = fmaf(A1, acc, B1);
}

// ---------------- K2: cosine-similarity GEMM + inline norms ------------------
__global__ void __launch_bounds__(256) cos_kernel(const float* __restrict__ t,
                                                  const float* __restrict__ s) {
    int b = blockIdx.z;
    int m0 = blockIdx.y * 64;
    int n0 = blockIdx.x * 64;
    __shared__ float ts[16][64];
    __shared__ float ss[16][64];
    __shared__ float ntp[4][64], nsp[4][64];
    __shared__ float nts[64], nss[64];
    int tid = threadIdx.x, ty = tid >> 4, tx = tid & 15;
    float acc[4][4] = {};
    float tss = 0.f, sss = 0.f;
    const float* tb = t + (size_t)b * F_ * M_;
    const float* sb = s + (size_t)b * F_ * N_;
    for (int f0 = 0; f0 < F_; f0 += 16) {
        __syncthreads();
#pragma unroll
        for (int i = 0; i < 4; i++) {
            int e = tid + i * 256;
            int fr = e >> 6, cc = e & 63;
            float tv = tb[(f0 + fr) * M_ + m0 + cc];
            float sv = sb[(f0 + fr) * N_ + n0 + cc];
            ts[fr][cc] = tv; tss = fmaf(tv, tv, tss);
            ss[fr][cc] = sv; sss = fmaf(sv, sv, sss);
        }
        __syncthreads();
#pragma unroll
        for (int k = 0; k < 16; k++) {
            float4 av = *(const float4*)&ts[k][4 * ty];
            float4 bv = *(const float4*)&ss[k][4 * tx];
            float a0 = av.x, a1 = av.y, a2 = av.z, a3 = av.w;
            float b0 = bv.x, b1 = bv.y, b2 = bv.z, b3 = bv.w;
            acc[0][0] = fmaf(a0, b0, acc[0][0]); acc[0][1] = fmaf(a0, b1, acc[0][1]);
            acc[0][2] = fmaf(a0, b2, acc[0][2]); acc[0][3] = fmaf(a0, b3, acc[0][3]);
            acc[1][0] = fmaf(a1, b0, acc[1][0]); acc[1][1] = fmaf(a1, b1, acc[1][1]);
            acc[1][2] = fmaf(a1, b2, acc[1][2]); acc[1][3] = fmaf(a1, b3, acc[1][3]);
            acc[2][0] = fmaf(a2, b0, acc[2][0]); acc[2][1] = fmaf(a2, b1, acc[2][1]);
            acc[2][2] = fmaf(a2, b2, acc[2][2]); acc[2][3] = fmaf(a2, b3, acc[2][3]);
            acc[3][0] = fmaf(a3, b0, acc[3][0]); acc[3][1] = fmaf(a3, b1, acc[3][1]);
            acc[3][2] = fmaf(a3, b2, acc[3][2]); acc[3][3] = fmaf(a3, b3, acc[3][3]);
        }
    }
    // reduce norms: each column's sumsq is spread over 4 threads (tid mod 64)
    ntp[tid >> 6][tid & 63] = tss;
    nsp[tid >> 6][tid & 63] = sss;
    __syncthreads();
    if (tid < 64)
        nts[tid] = sqrtf(ntp[0][tid] + ntp[1][tid] + ntp[2][tid] + ntp[3][tid]);
    else if (tid < 128) {
        int c = tid - 64;
        nss[c] = sqrtf(nsp[0][c] + nsp[1][c] + nsp[2][c] + nsp[3][c]);
    }
    __syncthreads();
    float ntv[4], nsv[4];
#pragma unroll
    for (int r = 0; r < 4; r++) ntv[r] = nts[4 * ty + r];
#pragma unroll
    for (int c = 0; c < 4; c++) nsv[c] = nss[4 * tx + c];
#pragma unroll
    for (int c = 0; c < 4; c++) {
        int n = n0 + 4 * tx + c;
        float4 v;
        v.x = acc[0][c] / fmaxf(ntv[0] * nsv[c], 1e-8f);
        v.y = acc[1][c] / fmaxf(ntv[1] * nsv[c], 1e-8f);
        v.z = acc[2][c] / fmaxf(ntv[2] * nsv[c], 1e-8f);
        v.w = acc[3][c] / fmaxf(ntv[3] * nsv[c], 1e-8f);
        *(float4*)&d_cos[((size_t)b * N_ + n) * M_ + m0 + 4 * ty] = v;
    }
}

// ---------------- K3: fused MLP (2-segment fp16/bf16, K=128) -----------------
// SMEM map (bytes):
//  0       W2 image (16384)
//  16384   W3 image (16384)
//  32768   Xs [128 m][272B] split activations (34816)
//  67584   Ap tile [64 h][128 m] f32 (32768)
//  100352  red [8 nl][4 mb][64 g] f32 (8192)
//  108544  w0s (256) | 108800 b2s (256) | 109056 b3s (256)
#define XS_OFF   32768
#define AP_OFF   67584
#define RED_OFF  100352
#define W0_OFF   108544
#define B2_OFF   108800
#define B3_OFF   109056
#define MAIN_SMEM_BYTES 109312

// warp (gb,mb) computes [rows mb*32..+31] x [cols gb*32..+31]
// K=128 in 8 k16-steps: k 0-3 fp16 segment, k 4-7 bf16 segment
__device__ __forceinline__ void do_gemm(uint32_t xs_u32, uint32_t w_u32,
                                        int lane, int gb, int mb, float acc[2][4][4]) {
    uint32_t aaddr0 = xs_u32 + (uint32_t)((mb * 32 + (lane & 15)) * ROWB + ((lane >> 4) << 4));
    uint32_t aaddr1 = aaddr0 + 16 * ROWB;
    int kk = (lane & 7) + ((lane >> 3) & 1) * 8;
    int nc0 = gb * 4 + (lane >> 4);
    uint32_t baddr0 = w_u32 + (uint32_t)(kk * 128 + ((nc0 ^ (lane & 7)) << 4));
    uint32_t baddr1 = w_u32 + (uint32_t)(kk * 128 + (((nc0 + 2) ^ (lane & 7)) << 4));
#pragma unroll
    for (int k = 0; k < 8; k++) {
        uint32_t a0[4], a1[4], b0[4], b1[4];
        ldsm_x4 (a0, aaddr0 + k * 32);
        ldsm_x4 (a1, aaddr1 + k * 32);
        ldsm_x4t(b0, baddr0 + k * 2048);
        ldsm_x4t(b1, baddr1 + k * 2048);
        if (k < 4) {
            mma_f16(acc[0][0], a0, b0[0], b0[1]); mma_f16(acc[0][1], a0, b0[2], b0[3]);
            mma_f16(acc[0][2], a0, b1[0], b1[1]); mma_f16(acc[0][3], a0, b1[2], b1[3]);
            mma_f16(acc[1][0], a1, b0[0], b0[1]); mma_f16(acc[1][1], a1, b0[2], b0[3]);
            mma_f16(acc[1][2], a1, b1[0], b1[1]); mma_f16(acc[1][3], a1, b1[2], b1[3]);
        } else {
            mma_bf16(acc[0][0], a0, b0[0], b0[1]); mma_bf16(acc[0][1], a0, b0[2], b0[3]);
            mma_bf16(acc[0][2], a0, b1[0], b1[1]); mma_bf16(acc[0][3], a0, b1[2], b1[3]);
            mma_bf16(acc[1][0], a1, b0[0], b0[1]); mma_bf16(acc[1][1], a1, b0[2], b0[3]);
            mma_bf16(acc[1][2], a1, b1[0], b1[1]); mma_bf16(acc[1][3], a1, b1[2], b1[3]);
        }
    }
}

__global__ void __launch_bounds__(256, 2) main_kernel() {
    extern __shared__ char smem[];
    float* aps = (float*)(smem + AP_OFF);
    float* red = (float*)(smem + RED_OFF);
    float* w0s = (float*)(smem + W0_OFF);
    float* b2s = (float*)(smem + B2_OFF);
    float* b3s = (float*)(smem + B3_OFF);

    uint32_t sb32 = smem_to_u32(smem);
    uint32_t xs_u32 = sb32 + XS_OFF;

    int tid = threadIdx.x;
    int wid = tid >> 5, lane = tid & 31;
    int gb = wid >> 2, mb = wid & 3;
    int barid = mb + 1;
    int b = blockIdx.y;
    int n0 = blockIdx.x * NPB;

    // stage weights + biases; init red
    {
        const uint4* sw2 = (const uint4*)d_W2img;
        const uint4* sw3 = (const uint4*)d_W3img;
        uint4* dw2 = (uint4*)smem;
        uint4* dw3 = (uint4*)(smem + 16384);
#pragma unroll
        for (int i = 0; i < 4; i++) {
            dw2[tid + i * 256] = sw2[tid + i * 256];
            dw3[tid + i * 256] = sw3[tid + i * 256];
        }
        if (tid < 64) {
            w0s[tid] = d_w0[tid];
            b2s[tid] = d_b2v[tid];
            b3s[tid] = d_b3v[tid];
        }
#pragma unroll
        for (int i = 0; i < 8; i++) red[tid + i * 256] = 0.f;
    }

    for (int mt = 0; mt < 2; mt++) {
        __syncthreads();   // all readers of aps/Xs from prev phase done
        {
            const float4* ag = (const float4*)d_Ap;
            float4* as = (float4*)aps;
#pragma unroll
            for (int i = 0; i < 8; i++) {
                int e = tid + i * 256;
                int h = e >> 5, q = e & 31;
                as[e] = ag[((size_t)b * 64 + h) * 64 + mt * 32 + q];
            }
        }
        __syncthreads();

        for (int nl = 0; nl < NPB; nl++) {
            // ---- build X1 (pair-closed rows): thread -> row m = tid&127 ----
            {
                int m = tid & 127;
                int hb = (tid >> 7) * 32;
                float cv = __ldg(d_cos + ((size_t)b * N_ + n0 + nl) * M_ + mt * 128 + m);
                char* row = smem + XS_OFF + m * ROWB;
#pragma unroll
                for (int cc = 0; cc < 4; cc++) {
                    int h0 = hb + 8 * cc;
                    float y0 = fmaxf(fmaf(w0s[h0 + 0], cv, aps[(h0 + 0) * 128 + m]), 0.f);
                    float y1 = fmaxf(fmaf(w0s[h0 + 1], cv, aps[(h0 + 1) * 128 + m]), 0.f);
                    float y2 = fmaxf(fmaf(w0s[h0 + 2], cv, aps[(h0 + 2) * 128 + m]), 0.f);
                    float y3 = fmaxf(fmaf(w0s[h0 + 3], cv, aps[(h0 + 3) * 128 + m]), 0.f);
                    float y4 = fmaxf(fmaf(w0s[h0 + 4], cv, aps[(h0 + 4) * 128 + m]), 0.f);
                    float y5 = fmaxf(fmaf(w0s[h0 + 5], cv, aps[(h0 + 5) * 128 + m]), 0.f);
                    float y6 = fmaxf(fmaf(w0s[h0 + 6], cv, aps[(h0 + 6) * 128 + m]), 0.f);
                    float y7 = fmaxf(fmaf(w0s[h0 + 7], cv, aps[(h0 + 7) * 128 + m]), 0.f);
                    uint4 hh, ll;
                    hh.x = pack_f16(y0, y1);  ll.x = pack_bf16(y0, y1);
                    hh.y = pack_f16(y2, y3);  ll.y = pack_bf16(y2, y3);
                    hh.z = pack_f16(y4, y5);  ll.z = pack_bf16(y4, y5);
                    hh.w = pack_f16(y6, y7);  ll.w = pack_bf16(y6, y7);
                    *(uint4*)(row + h0 * 2)       = hh;
                    *(uint4*)(row + 128 + h0 * 2) = ll;
                }
            }
            BARP(barid);

            // ---- GEMM1: W2f @ X1 ----
            float acc[2][4][4] = {};
            do_gemm(xs_u32, sb32, lane, gb, mb, acc);
            BARP(barid);   // pair done reading rows mb before overwrite

            // ---- epilogue 1: relu(+b2), pack fp16+bf16, stmatrix ----
            {
                int j = lane >> 3, r = lane & 7;
                int g0 = gb * 32 + 2 * (lane & 3);
                uint32_t adbase = xs_u32
                    + (uint32_t)((mb * 32 + (j & 1) * 8 + r) * ROWB + gb * 64 + (j >> 1) * 16);
#pragma unroll
                for (int i = 0; i < 2; i++) {
#pragma unroll
                    for (int tp = 0; tp < 2; tp++) {
                        int t0 = 2 * tp, t1 = t0 + 1;
                        float b00 = b2s[g0 + 8 * t0], b01 = b2s[g0 + 8 * t0 + 1];
                        float b10 = b2s[g0 + 8 * t1], b11 = b2s[g0 + 8 * t1 + 1];
                        float y00 = fmaxf(acc[i][t0][0] + b00, 0.f);
                        float y01 = fmaxf(acc[i][t0][1] + b01, 0.f);
                        float y02 = fmaxf(acc[i][t0][2] + b00, 0.f);
                        float y03 = fmaxf(acc[i][t0][3] + b01, 0.f);
                        float y10 = fmaxf(acc[i][t1][0] + b10, 0.f);
                        float y11 = fmaxf(acc[i][t1][1] + b11, 0.f);
                        float y12 = fmaxf(acc[i][t1][2] + b10, 0.f);
                        float y13 = fmaxf(acc[i][t1][3] + b11, 0.f);
                        uint32_t hh[4], ll[4];
                        hh[0] = pack_f16(y00, y01);  ll[0] = pack_bf16(y00, y01);
                        hh[1] = pack_f16(y02, y03);  ll[1] = pack_bf16(y02, y03);
                        hh[2] = pack_f16(y10, y11);  ll[2] = pack_bf16(y10, y11);
                        hh[3] = pack_f16(y12, y13);  ll[3] = pack_bf16(y12, y13);
                        uint32_t ad = adbase + (uint32_t)(i * 16 * ROWB + t0 * 16);
                        stsm_x4(ad, hh);
                        stsm_x4(ad + 128, ll);
                    }
                }
            }
            BARP(barid);

            // ---- GEMM2: W3f @ X2 ----
            float acc2[2][4][4] = {};
            do_gemm(xs_u32, sb32 + 16384, lane, gb, mb, acc2);

            // ---- epilogue 2: relu(+b3), max over m -> red RMW (race-free) ----
            {
                int g0 = gb * 32 + 2 * (lane & 3);
#pragma unroll
                for (int t = 0; t < 4; t++) {
#pragma unroll
                    for (int d = 0; d < 2; d++) {
                        int gg = g0 + d + 8 * t;
                        float v = fmaxf(fmaxf(acc2[0][t][d], acc2[0][t][2 + d]),
                                        fmaxf(acc2[1][t][d], acc2[1][t][2 + d]));
                        v = fmaxf(v + b3s[gg], 0.f);
                        v = fmaxf(v, __shfl_xor_sync(0xFFFFFFFFu, v, 4));
                        v = fmaxf(v, __shfl_xor_sync(0xFFFFFFFFu, v, 8));
                        v = fmaxf(v, __shfl_xor_sync(0xFFFFFFFFu, v, 16));
                        if (lane < 4) {
                            int ri = nl * 256 + mb * 64 + gg;
                            red[ri] = fmaxf(red[ri], v);
                        }
                    }
                }
            }
            BARP(barid);   // pair done reading rows mb before next build
        }
    }

    // final pooled reduce + write (8 nl x 64 h = 512 outputs, 2 per thread)
    __syncthreads();
#pragma unroll
    for (int i = 0; i < 2; i++) {
        int e = tid + i * 256;
        int nl = e >> 6, h = e & 63;
        const float* r = red + nl * 256;
        float v = fmaxf(fmaxf(r[h], r[64 + h]), fmaxf(r[128 + h], r[192 + h]));
        d_p[((size_t)b * N_ + n0 + nl) * H_ + h] = v;
    }
}

// ---------------- K4: head (Wc1 -> relu -> Wc2 + bc2) ------------------------
#define HEAD_SMEM_FLOATS 20608
__global__ void __launch_bounds__(256) head_kernel(const float* __restrict__ bc2,
                                                   float* __restrict__ out) {
    extern __shared__ float smf[];
    float* wc1s = smf;
    float* wc2s = smf + 4096;
    float* ps   = smf + 12288;
    float* cs   = smf + 16384;
    float* bc1s = smf + 20544;

    int b = blockIdx.y, n0 = blockIdx.x * 64;
    int tid = threadIdx.x;
#pragma unroll
    for (int i = 0; i < 16; i++) {
        int idx = tid + i * 256;
        wc1s[idx] = d_Wc1t[idx];
        ps[idx]   = d_p[((size_t)b * N_ + n0) * H_ + idx];
    }
#pragma unroll
    for (int i = 0; i < 32; i++) {
        int idx = tid + i * 256;
        wc2s[idx] = d_Wc2t[idx];
    }
    if (tid < 64) bc1s[tid] = d_bc1v[tid];
    __syncthreads();

#pragma unroll
    for (int i = 0; i < 16; i++) {
        int idx = tid + i * 256;
        int nn = idx >> 6, g = idx & 63;
        float acc = bc1s[g];
#pragma unroll 16
        for (int h = 0; h < 64; h++) acc = fmaf(wc1s[h * 64 + g], ps[nn * 64 + h], acc);
        cs[nn * 65 + g] = fmaxf(acc, 0.f);
    }
    __syncthreads();

#pragma unroll
    for (int i = 0; i < 32; i++) {
        int idx = tid + i * 256;
        int o = idx >> 6, nn = idx & 63;
        float acc = __ldg(bc2 + o);
#pragma unroll 16
        for (int h = 0; h < 64; h++) acc = fmaf(wc2s[h * 128 + o], cs[nn * 65 + h], acc);
        out[((size_t)b * O_ + o) * N_ + n0 + nn] = acc;
    }
}

// ---------------- launch ------------------------------------------------------
extern "C" void kernel_launch(void* const* d_in, const int* in_sizes, int n_in,
                              void* d_out, int out_size) {
    const float* t   = (const float*)d_in[0];
    const float* s   = (const float*)d_in[1];
    const float* W1  = (const float*)d_in[2];
    const float* W2  = (const float*)d_in[3];
    const float* W3  = (const float*)d_in[4];
    const float* Wc1 = (const float*)d_in[5];
    const float* Wc2 = (const float*)d_in[6];
    const float* bc2 = (const float*)d_in[7];
    const float* g1 = (const float*)d_in[8],  *b1 = (const float*)d_in[9];
    const float* m1 = (const float*)d_in[10], *v1 = (const float*)d_in[11];
    const float* g2 = (const float*)d_in[12], *b2 = (const float*)d_in[13];
    const float* m2 = (const float*)d_in[14], *v2 = (const float*)d_in[15];
    const float* g3 = (const float*)d_in[16], *b3 = (const float*)d_in[17];
    const float* m3 = (const float*)d_in[18], *v3 = (const float*)d_in[19];
    const float* gc1 = (const float*)d_in[20], *bc1 = (const float*)d_in[21];
    const float* mc1 = (const float*)d_in[22], *vc1 = (const float*)d_in[23];
    float* out = (float*)d_out;

    cudaFuncSetAttribute(main_kernel, cudaFuncAttributeMaxDynamicSharedMemorySize,
                         MAIN_SMEM_BYTES);
    cudaFuncSetAttribute(head_kernel, cudaFuncAttributeMaxDynamicSharedMemorySize,
                         HEAD_SMEM_FLOATS * 4);

    fold_kernel<<<1, 256>>>(W1, W2, W3, Wc1, Wc2, g1, v1,
                            g2, b2, m2, v2, g3, b3, m3, v3, gc1, bc1, mc1, vc1);
    ap_kernel<<<B_ * H_, 256>>>(t, W1, g1, b1, m1, v1);
    cos_kernel<<<dim3(N_ / 64, M_ / 64, B_), 256>>>(t, s);
    main_kernel<<<dim3(N_ / NPB, B_), 256, MAIN_SMEM_BYTES>>>();
    head_kernel<<<dim3(N_ / 64, B_), 256, HEAD_SMEM_FLOATS * 4>>>(bc2, out);
}

// round 14
// speedup vs baseline: 1.8755x; 1.1801x over previous
#include <cuda_runtime.h>
#include <cuda_bf16.h>
#include <cuda_fp16.h>
#include <cstdint>

#define B_ 8
#define F_ 128
#define M_ 256
#define N_ 1024
#define H_ 64
#define O_ 128
#define NPB 8
#define ROWB 144   // X row bytes: 128 fp16 + 16 pad

// ---------------- scratch (device globals; no allocations allowed) ----------
__device__ __align__(16) float d_cos[B_ * N_ * M_];   // [b][n][m]
__device__ __align__(16) float d_Ap [B_ * H_ * M_];   // [b][h][m]
__device__ float d_w0 [H_];
__device__ float d_b2v[H_], d_b3v[H_], d_bc1v[H_];
// fp16 weight images [k=64 rows][64 g], 128B rows, 16B-chunk XOR swizzle
__device__ __align__(16) unsigned short d_W2img[64 * 64];
__device__ __align__(16) unsigned short d_W3img[64 * 64];
__device__ __align__(16) float d_Wc1t[H_ * H_];
__device__ __align__(16) float d_Wc2t[H_ * O_];
__device__ __align__(16) float d_p  [B_ * N_ * H_];

// ================= tensor-core helpers (sm_80/90 PTX, valid on sm_103) ======
__device__ __forceinline__ uint32_t smem_to_u32(const void* p) {
    uint32_t a;
    asm("{ .reg .u64 t; cvta.to.shared.u64 t, %1; cvt.u32.u64 %0, t; }" : "=r"(a) : "l"(p));
    return a;
}
__device__ __forceinline__ void ldsm_x4(uint32_t r[4], uint32_t addr) {
    asm volatile("ldmatrix.sync.aligned.m8n8.x4.shared.b16 {%0,%1,%2,%3}, [%4];"
                 : "=r"(r[0]), "=r"(r[1]), "=r"(r[2]), "=r"(r[3]) : "r"(addr));
}
__device__ __forceinline__ void ldsm_x4t(uint32_t r[4], uint32_t addr) {
    asm volatile("ldmatrix.sync.aligned.m8n8.x4.trans.shared.b16 {%0,%1,%2,%3}, [%4];"
                 : "=r"(r[0]), "=r"(r[1]), "=r"(r[2]), "=r"(r[3]) : "r"(addr));
}
__device__ __forceinline__ void stsm_x4(uint32_t addr, const uint32_t r[4]) {
    asm volatile("stmatrix.sync.aligned.m8n8.x4.shared.b16 [%0], {%1,%2,%3,%4};"
                 :: "r"(addr), "r"(r[0]), "r"(r[1]), "r"(r[2]), "r"(r[3]) : "memory");
}
__device__ __forceinline__ void mma_f16(float d[4], const uint32_t a[4],
                                        uint32_t b0, uint32_t b1) {
    asm volatile("mma.sync.aligned.m16n8k16.row.col.f32.f16.f16.f32 "
                 "{%0,%1,%2,%3}, {%4,%5,%6,%7}, {%8,%9}, {%0,%1,%2,%3};"
                 : "+f"(d[0]), "+f"(d[1]), "+f"(d[2]), "+f"(d[3])
                 : "r"(a[0]), "r"(a[1]), "r"(a[2]), "r"(a[3]), "r"(b0), "r"(b1));
}
// 2-warp pair barrier (warps mb and mb+4), named barrier id = mb+1
#define BARP(id) asm volatile("bar.sync %0, 64;" :: "r"(id) : "memory")

__device__ __forceinline__ uint32_t pack_f16(float y0, float y1) {
    __half2 h = __floats2half2_rn(y0, y1);      // y0 in low half
    return *reinterpret_cast<uint32_t*>(&h);
}

// ---------------- K0: fold BN into weights, emit fp16 images -----------------
__global__ void fold_kernel(const float* __restrict__ W1, const float* __restrict__ W2,
                            const float* __restrict__ W3, const float* __restrict__ Wc1,
                            const float* __restrict__ Wc2,
                            const float* __restrict__ g1, const float* __restrict__ v1,
                            const float* __restrict__ g2, const float* __restrict__ b2,
                            const float* __restrict__ m2, const float* __restrict__ v2,
                            const float* __restrict__ g3, const float* __restrict__ b3,
                            const float* __restrict__ m3, const float* __restrict__ v3,
                            const float* __restrict__ gc1, const float* __restrict__ bc1,
                            const float* __restrict__ mc1, const float* __restrict__ vc1) {
    __shared__ float a2s[H_], a3s[H_], ac1s[H_];
    int tid = threadIdx.x;
    if (tid < H_) {
        float A1 = g1[tid] * rsqrtf(v1[tid] + 1e-5f);
        d_w0[tid] = A1 * W1[tid * (F_ + 1)];
        float A2 = g2[tid] * rsqrtf(v2[tid] + 1e-5f);
        a2s[tid] = A2;  d_b2v[tid] = b2[tid] - A2 * m2[tid];
        float A3 = g3[tid] * rsqrtf(v3[tid] + 1e-5f);
        a3s[tid] = A3;  d_b3v[tid] = b3[tid] - A3 * m3[tid];
        float Ac = gc1[tid] * rsqrtf(vc1[tid] + 1e-5f);
        ac1s[tid] = Ac; d_bc1v[tid] = bc1[tid] - Ac * mc1[tid];
    }
    __syncthreads();
    // image rows k = h (0..63), columns g
    for (int i = tid; i < 64 * 64; i += 256) {
        int k = i >> 6, g = i & 63;
        float w2v = a2s[g] * W2[g * H_ + k];
        float w3v = a3s[g] * W3[g * H_ + k];
        uint32_t off = (uint32_t)k * 128u + ((((uint32_t)g >> 3) ^ ((uint32_t)k & 7u)) << 4)
                       + (((uint32_t)g & 7u) << 1);
        d_W2img[off >> 1] = __half_as_ushort(__float2half_rn(w2v));
        d_W3img[off >> 1] = __half_as_ushort(__float2half_rn(w3v));
    }
    for (int i = tid; i < H_ * H_; i += 256) {
        int k = i >> 6, g = i & 63;
        d_Wc1t[k * H_ + g] = ac1s[g] * Wc1[g * H_ + k];
    }
    for (int i = tid; i < H_ * O_; i += 256) {
        int h = i >> 7, o = i & 127;
        d_Wc2t[h * O_ + o] = Wc2[o * H_ + h];
    }
}

// ---------------- K1: A' = BN1-folded W1[:,1:] @ t ---------------------------
__global__ void ap_kernel(const float* __restrict__ t, const float* __restrict__ W1,
                          const float* __restrict__ g1, const float* __restrict__ b1,
                          const float* __restrict__ m1, const float* __restrict__ v1) {
    int bh = blockIdx.x;
    int b = bh >> 6, h = bh & 63;
    int m = threadIdx.x;
    __shared__ float w[F_];
    if (m < F_) w[m] = W1[h * (F_ + 1) + 1 + m];
    __syncthreads();
    const float* tp = t + (size_t)b * F_ * M_ + m;
    float acc = 0.f;
#pragma unroll 8
    for (int f = 0; f < F_; f++) acc = fmaf(w[f], tp[f * M_], acc);
    float A1 = g1[h] * rsqrtf(v1[h] + 1e-5f);
    float B1 = b1[h] - A1 * m1[h];
    d_Ap[bh * M_ + m] = fmaf(A1, acc, B1);
}

// ---------------- K2: cosine-similarity GEMM + inline norms ------------------
__global__ void __launch_bounds__(256) cos_kernel(const float* __restrict__ t,
                                                  const float* __restrict__ s) {
    int b = blockIdx.z;
    int m0 = blockIdx.y * 64;
    int n0 = blockIdx.x * 64;
    __shared__ float ts[16][64];
    __shared__ float ss[16][64];
    __shared__ float ntp[4][64], nsp[4][64];
    __shared__ float nts[64], nss[64];
    int tid = threadIdx.x, ty = tid >> 4, tx = tid & 15;
    float acc[4][4] = {};
    float tss = 0.f, sss = 0.f;
    const float* tb = t + (size_t)b * F_ * M_;
    const float* sb = s + (size_t)b * F_ * N_;
    for (int f0 = 0; f0 < F_; f0 += 16) {
        __syncthreads();
#pragma unroll
        for (int i = 0; i < 4; i++) {
            int e = tid + i * 256;
            int fr = e >> 6, cc = e & 63;
            float tv = tb[(f0 + fr) * M_ + m0 + cc];
            float sv = sb[(f0 + fr) * N_ + n0 + cc];
            ts[fr][cc] = tv; tss = fmaf(tv, tv, tss);
            ss[fr][cc] = sv; sss = fmaf(sv, sv, sss);
        }
        __syncthreads();
#pragma unroll
        for (int k = 0; k < 16; k++) {
            float4 av = *(const float4*)&ts[k][4 * ty];
            float4 bv = *(const float4*)&ss[k][4 * tx];
            float a0 = av.x, a1 = av.y, a2 = av.z, a3 = av.w;
            float b0 = bv.x, b1 = bv.y, b2 = bv.z, b3 = bv.w;
            acc[0][0] = fmaf(a0, b0, acc[0][0]); acc[0][1] = fmaf(a0, b1, acc[0][1]);
            acc[0][2] = fmaf(a0, b2, acc[0][2]); acc[0][3] = fmaf(a0, b3, acc[0][3]);
            acc[1][0] = fmaf(a1, b0, acc[1][0]); acc[1][1] = fmaf(a1, b1, acc[1][1]);
            acc[1][2] = fmaf(a1, b2, acc[1][2]); acc[1][3] = fmaf(a1, b3, acc[1][3]);
            acc[2][0] = fmaf(a2, b0, acc[2][0]); acc[2][1] = fmaf(a2, b1, acc[2][1]);
            acc[2][2] = fmaf(a2, b2, acc[2][2]); acc[2][3] = fmaf(a2, b3, acc[2][3]);
            acc[3][0] = fmaf(a3, b0, acc[3][0]); acc[3][1] = fmaf(a3, b1, acc[3][1]);
            acc[3][2] = fmaf(a3, b2, acc[3][2]); acc[3][3] = fmaf(a3, b3, acc[3][3]);
        }
    }
    ntp[tid >> 6][tid & 63] = tss;
    nsp[tid >> 6][tid & 63] = sss;
    __syncthreads();
    if (tid < 64)
        nts[tid] = sqrtf(ntp[0][tid] + ntp[1][tid] + ntp[2][tid] + ntp[3][tid]);
    else if (tid < 128) {
        int c = tid - 64;
        nss[c] = sqrtf(nsp[0][c] + nsp[1][c] + nsp[2][c] + nsp[3][c]);
    }
    __syncthreads();
    float ntv[4], nsv[4];
#pragma unroll
    for (int r = 0; r < 4; r++) ntv[r] = nts[4 * ty + r];
#pragma unroll
    for (int c = 0; c < 4; c++) nsv[c] = nss[4 * tx + c];
#pragma unroll
    for (int c = 0; c < 4; c++) {
        int n = n0 + 4 * tx + c;
        float4 v;
        v.x = acc[0][c] / fmaxf(ntv[0] * nsv[c], 1e-8f);
        v.y = acc[1][c] / fmaxf(ntv[1] * nsv[c], 1e-8f);
        v.z = acc[2][c] / fmaxf(ntv[2] * nsv[c], 1e-8f);
        v.w = acc[3][c] / fmaxf(ntv[3] * nsv[c], 1e-8f);
        *(float4*)&d_cos[((size_t)b * N_ + n) * M_ + m0 + 4 * ty] = v;
    }
}

// ---------------- K3: fused MLP (single fp16 segment, K=64) ------------------
// SMEM map (bytes):
//  0       W2 image (8192)
//  8192    W3 image (8192)
//  16384   Xs [128 m][144B] fp16 activations (18432)
//  34816   aps [128 m][68 f] f32 (34816)
//  69632   red [8 nl][4 mb][64 g] f32 (8192)
//  77824   w0s (256) | 78080 b2s (256) | 78336 b3s (256)
#define XS_OFF   16384
#define AP_OFF   34816
#define RED_OFF  69632
#define W0_OFF   77824
#define B2_OFF   78080
#define B3_OFF   78336
#define MAIN_SMEM_BYTES 78592

// warp (gb,mb) computes [rows mb*32..+31] x [cols gb*32..+31], K=64 fp16
__device__ __forceinline__ void do_gemm(uint32_t xs_u32, uint32_t w_u32,
                                        int lane, int gb, int mb, float acc[2][4][4]) {
    uint32_t aaddr0 = xs_u32 + (uint32_t)((mb * 32 + (lane & 15)) * ROWB + ((lane >> 4) << 4));
    uint32_t aaddr1 = aaddr0 + 16 * ROWB;
    int kk = (lane & 7) + ((lane >> 3) & 1) * 8;
    int nc0 = gb * 4 + (lane >> 4);
    uint32_t baddr0 = w_u32 + (uint32_t)(kk * 128 + ((nc0 ^ (lane & 7)) << 4));
    uint32_t baddr1 = w_u32 + (uint32_t)(kk * 128 + (((nc0 + 2) ^ (lane & 7)) << 4));
#pragma unroll
    for (int k = 0; k < 4; k++) {
        uint32_t a0[4], a1[4], b0[4], b1[4];
        ldsm_x4 (a0, aaddr0 + k * 32);
        ldsm_x4 (a1, aaddr1 + k * 32);
        ldsm_x4t(b0, baddr0 + k * 2048);
        ldsm_x4t(b1, baddr1 + k * 2048);
        mma_f16(acc[0][0], a0, b0[0], b0[1]); mma_f16(acc[0][1], a0, b0[2], b0[3]);
        mma_f16(acc[0][2], a0, b1[0], b1[1]); mma_f16(acc[0][3], a0, b1[2], b1[3]);
        mma_f16(acc[1][0], a1, b0[0], b0[1]); mma_f16(acc[1][1], a1, b0[2], b0[3]);
        mma_f16(acc[1][2], a1, b1[0], b1[1]); mma_f16(acc[1][3], a1, b1[2], b1[3]);
    }
}

__global__ void __launch_bounds__(256, 2) main_kernel() {
    extern __shared__ char smem[];
    float* aps = (float*)(smem + AP_OFF);   // [m][68]
    float* red = (float*)(smem + RED_OFF);
    float* w0s = (float*)(smem + W0_OFF);
    float* b2s = (float*)(smem + B2_OFF);
    float* b3s = (float*)(smem + B3_OFF);

    uint32_t sb32 = smem_to_u32(smem);
    uint32_t xs_u32 = sb32 + XS_OFF;

    int tid = threadIdx.x;
    int wid = tid >> 5, lane = tid & 31;
    int gb = wid >> 2, mb = wid & 3;
    int barid = mb + 1;
    int b = blockIdx.y;
    int n0 = blockIdx.x * NPB;

    // stage weights + biases; init red
    {
        const uint4* sw2 = (const uint4*)d_W2img;
        const uint4* sw3 = (const uint4*)d_W3img;
        uint4* dw2 = (uint4*)smem;
        uint4* dw3 = (uint4*)(smem + 8192);
#pragma unroll
        for (int i = 0; i < 2; i++) {
            dw2[tid + i * 256] = sw2[tid + i * 256];
            dw3[tid + i * 256] = sw3[tid + i * 256];
        }
        if (tid < 64) {
            w0s[tid] = d_w0[tid];
            b2s[tid] = d_b2v[tid];
            b3s[tid] = d_b3v[tid];
        }
#pragma unroll
        for (int i = 0; i < 8; i++) red[tid + i * 256] = 0.f;
    }

    for (int mt = 0; mt < 2; mt++) {
        __syncthreads();   // all readers of aps/Xs from prev phase done
        // stage Ap transposed into aps[m][68]: float4-coalesced read over m,
        // scatter the 4 m-values. 2048 float4 = full 64h x 128m coverage.
#pragma unroll
        for (int i = 0; i < 8; i++) {
            int e = tid + i * 256;           // 0..2047
            int h = e >> 5, q = e & 31;      // h in [0,64), q in [0,32)
            float4 v = *(const float4*)(d_Ap + ((size_t)b * H_ + h) * M_ + mt * 128 + 4 * q);
            aps[(4 * q + 0) * 68 + h] = v.x;
            aps[(4 * q + 1) * 68 + h] = v.y;
            aps[(4 * q + 2) * 68 + h] = v.z;
            aps[(4 * q + 3) * 68 + h] = v.w;
        }
        __syncthreads();

        for (int nl = 0; nl < NPB; nl++) {
            // ---- build X1 (pair-closed rows): thread -> row m = tid&127 ----
            {
                int m = tid & 127;
                int hb = (tid >> 7) * 32;
                float cv = __ldg(d_cos + ((size_t)b * N_ + n0 + nl) * M_ + mt * 128 + m);
                char* row = smem + XS_OFF + m * ROWB;
                const float* ar = aps + m * 68 + hb;
#pragma unroll
                for (int cc = 0; cc < 4; cc++) {
                    int h0 = hb + 8 * cc;
                    float4 a0 = *(const float4*)(ar + 8 * cc);
                    float4 a1 = *(const float4*)(ar + 8 * cc + 4);
                    float y0 = fmaxf(fmaf(w0s[h0 + 0], cv, a0.x), 0.f);
                    float y1 = fmaxf(fmaf(w0s[h0 + 1], cv, a0.y), 0.f);
                    float y2 = fmaxf(fmaf(w0s[h0 + 2], cv, a0.z), 0.f);
                    float y3 = fmaxf(fmaf(w0s[h0 + 3], cv, a0.w), 0.f);
                    float y4 = fmaxf(fmaf(w0s[h0 + 4], cv, a1.x), 0.f);
                    float y5 = fmaxf(fmaf(w0s[h0 + 5], cv, a1.y), 0.f);
                    float y6 = fmaxf(fmaf(w0s[h0 + 6], cv, a1.z), 0.f);
                    float y7 = fmaxf(fmaf(w0s[h0 + 7], cv, a1.w), 0.f);
                    uint4 hh;
                    hh.x = pack_f16(y0, y1);
                    hh.y = pack_f16(y2, y3);
                    hh.z = pack_f16(y4, y5);
                    hh.w = pack_f16(y6, y7);
                    *(uint4*)(row + h0 * 2) = hh;
                }
            }
            BARP(barid);

            // ---- GEMM1: W2f @ X1 ----
            float acc[2][4][4] = {};
            do_gemm(xs_u32, sb32, lane, gb, mb, acc);
            BARP(barid);   // pair done reading rows mb before overwrite

            // ---- epilogue 1: relu(+b2), pack fp16, stmatrix into own rows ----
            {
                int j = lane >> 3, r = lane & 7;
                int g0 = gb * 32 + 2 * (lane & 3);
                uint32_t adbase = xs_u32
                    + (uint32_t)((mb * 32 + (j & 1) * 8 + r) * ROWB + gb * 64 + (j >> 1) * 16);
#pragma unroll
                for (int i = 0; i < 2; i++) {
#pragma unroll
                    for (int tp = 0; tp < 2; tp++) {
                        int t0 = 2 * tp, t1 = t0 + 1;
                        float b00 = b2s[g0 + 8 * t0], b01 = b2s[g0 + 8 * t0 + 1];
                        float b10 = b2s[g0 + 8 * t1], b11 = b2s[g0 + 8 * t1 + 1];
                        uint32_t hh[4];
                        hh[0] = pack_f16(fmaxf(acc[i][t0][0] + b00, 0.f),
                                         fmaxf(acc[i][t0][1] + b01, 0.f));
                        hh[1] = pack_f16(fmaxf(acc[i][t0][2] + b00, 0.f),
                                         fmaxf(acc[i][t0][3] + b01, 0.f));
                        hh[2] = pack_f16(fmaxf(acc[i][t1][0] + b10, 0.f),
                                         fmaxf(acc[i][t1][1] + b11, 0.f));
                        hh[3] = pack_f16(fmaxf(acc[i][t1][2] + b10, 0.f),
                                         fmaxf(acc[i][t1][3] + b11, 0.f));
                        stsm_x4(adbase + (uint32_t)(i * 16 * ROWB + t0 * 16), hh);
                    }
                }
            }
            BARP(barid);

            // ---- GEMM2: W3f @ X2 ----
            float acc2[2][4][4] = {};
            do_gemm(xs_u32, sb32 + 8192, lane, gb, mb, acc2);

            // ---- epilogue 2: relu(+b3), max over m -> red RMW (race-free) ----
            {
                int g0 = gb * 32 + 2 * (lane & 3);
#pragma unroll
                for (int t = 0; t < 4; t++) {
#pragma unroll
                    for (int d = 0; d < 2; d++) {
                        int gg = g0 + d + 8 * t;
                        float v = fmaxf(fmaxf(acc2[0][t][d], acc2[0][t][2 + d]),
                                        fmaxf(acc2[1][t][d], acc2[1][t][2 + d]));
                        v = fmaxf(v + b3s[gg], 0.f);
                        v = fmaxf(v, __shfl_xor_sync(0xFFFFFFFFu, v, 4));
                        v = fmaxf(v, __shfl_xor_sync(0xFFFFFFFFu, v, 8));
                        v = fmaxf(v, __shfl_xor_sync(0xFFFFFFFFu, v, 16));
                        if (lane < 4) {
                            int ri = nl * 256 + mb * 64 + gg;
                            red[ri] = fmaxf(red[ri], v);
                        }
                    }
                }
            }
            BARP(barid);   // pair done reading rows mb before next build
        }
    }

    // final pooled reduce + write (8 nl x 64 h = 512 outputs, 2 per thread)
    __syncthreads();
#pragma unroll
    for (int i = 0; i < 2; i++) {
        int e = tid + i * 256;
        int nl = e >> 6, h = e & 63;
        const float* r = red + nl * 256;
        float v = fmaxf(fmaxf(r[h], r[64 + h]), fmaxf(r[128 + h], r[192 + h]));
        d_p[((size_t)b * N_ + n0 + nl) * H_ + h] = v;
    }
}

// ---------------- K4: head (Wc1 -> relu -> Wc2 + bc2) ------------------------
#define HEAD_SMEM_FLOATS 20608
__global__ void __launch_bounds__(256) head_kernel(const float* __restrict__ bc2,
                                                   float* __restrict__ out) {
    extern __shared__ float smf[];
    float* wc1s = smf;
    float* wc2s = smf + 4096;
    float* ps   = smf + 12288;
    float* cs   = smf + 16384;
    float* bc1s = smf + 20544;

    int b = blockIdx.y, n0 = blockIdx.x * 64;
    int tid = threadIdx.x;
#pragma unroll
    for (int i = 0; i < 16; i++) {
        int idx = tid + i * 256;
        wc1s[idx] = d_Wc1t[idx];
        ps[idx]   = d_p[((size_t)b * N_ + n0) * H_ + idx];
    }
#pragma unroll
    for (int i = 0; i < 32; i++) {
        int idx = tid + i * 256;
        wc2s[idx] = d_Wc2t[idx];
    }
    if (tid < 64) bc1s[tid] = d_bc1v[tid];
    __syncthreads();

#pragma unroll
    for (int i = 0; i < 16; i++) {
        int idx = tid + i * 256;
        int nn = idx >> 6, g = idx & 63;
        float acc = bc1s[g];
#pragma unroll 16
        for (int h = 0; h < 64; h++) acc = fmaf(wc1s[h * 64 + g], ps[nn * 64 + h], acc);
        cs[nn * 65 + g] = fmaxf(acc, 0.f);
    }
    __syncthreads();

#pragma unroll
    for (int i = 0; i < 32; i++) {
        int idx = tid + i * 256;
        int o = idx >> 6, nn = idx & 63;
        float acc = __ldg(bc2 + o);
#pragma unroll 16
        for (int h = 0; h < 64; h++) acc = fmaf(wc2s[h * 128 + o], cs[nn * 65 + h], acc);
        out[((size_t)b * O_ + o) * N_ + n0 + nn] = acc;
    }
}

// ---------------- launch ------------------------------------------------------
extern "C" void kernel_launch(void* const* d_in, const int* in_sizes, int n_in,
                              void* d_out, int out_size) {
    const float* t   = (const float*)d_in[0];
    const float* s   = (const float*)d_in[1];
    const float* W1  = (const float*)d_in[2];
    const float* W2  = (const float*)d_in[3];
    const float* W3  = (const float*)d_in[4];
    const float* Wc1 = (const float*)d_in[5];
    const float* Wc2 = (const float*)d_in[6];
    const float* bc2 = (const float*)d_in[7];
    const float* g1 = (const float*)d_in[8],  *b1 = (const float*)d_in[9];
    const float* m1 = (const float*)d_in[10], *v1 = (const float*)d_in[11];
    const float* g2 = (const float*)d_in[12], *b2 = (const float*)d_in[13];
    const float* m2 = (const float*)d_in[14], *v2 = (const float*)d_in[15];
    const float* g3 = (const float*)d_in[16], *b3 = (const float*)d_in[17];
    const float* m3 = (const float*)d_in[18], *v3 = (const float*)d_in[19];
    const float* gc1 = (const float*)d_in[20], *bc1 = (const float*)d_in[21];
    const float* mc1 = (const float*)d_in[22], *vc1 = (const float*)d_in[23];
    float* out = (float*)d_out;

    cudaFuncSetAttribute(main_kernel, cudaFuncAttributeMaxDynamicSharedMemorySize,
                         MAIN_SMEM_BYTES);
    cudaFuncSetAttribute(head_kernel, cudaFuncAttributeMaxDynamicSharedMemorySize,
                         HEAD_SMEM_FLOATS * 4);

    fold_kernel<<<1, 256>>>(W1, W2, W3, Wc1, Wc2, g1, v1,
                            g2, b2, m2, v2, g3, b3, m3, v3, gc1, bc1, mc1, vc1);
    ap_kernel<<<B_ * H_, 256>>>(t, W1, g1, b1, m1, v1);
    cos_kernel<<<dim3(N_ / 64, M_ / 64, B_), 256>>>(t, s);
    main_kernel<<<dim3(N_ / NPB, B_), 256, MAIN_SMEM_BYTES>>>();
    head_kernel<<<dim3(N_ / 64, B_), 256, HEAD_SMEM_FLOATS * 4>>>(bc2, out);
}

// round 15
// speedup vs baseline: 1.9220x; 1.0248x over previous
#include <cuda_runtime.h>
#include <cuda_bf16.h>
#include <cuda_fp16.h>
#include <cstdint>

#define B_ 8
#define F_ 128
#define M_ 256
#define N_ 1024
#define H_ 64
#define O_ 128
#define NPB 8
#define ROWB 144   // X row bytes: 128 fp16 + 16 pad

// ---------------- scratch (device globals; no allocations allowed) ----------
__device__ __align__(16) float d_cos[B_ * N_ * M_];   // [b][n][m]
__device__ __align__(16) float d_Ap [B_ * H_ * M_];   // [b][h][m]
__device__ float d_w0 [H_];
__device__ float d_b2v[H_], d_b3v[H_], d_bc1v[H_];
// fp16 weight images [k=64 rows][64 g], 128B rows, 16B-chunk XOR swizzle
__device__ __align__(16) unsigned short d_W2img[64 * 64];
__device__ __align__(16) unsigned short d_W3img[64 * 64];
__device__ __align__(16) float d_Wc1t[H_ * H_];   // [h][g], BNc1-folded
__device__ __align__(16) float d_Wc2t[H_ * O_];   // [h][o]

// ================= tensor-core helpers (sm_80/90 PTX, valid on sm_103) ======
__device__ __forceinline__ uint32_t smem_to_u32(const void* p) {
    uint32_t a;
    asm("{ .reg .u64 t; cvta.to.shared.u64 t, %1; cvt.u32.u64 %0, t; }" : "=r"(a) : "l"(p));
    return a;
}
__device__ __forceinline__ void ldsm_x4(uint32_t r[4], uint32_t addr) {
    asm volatile("ldmatrix.sync.aligned.m8n8.x4.shared.b16 {%0,%1,%2,%3}, [%4];"
                 : "=r"(r[0]), "=r"(r[1]), "=r"(r[2]), "=r"(r[3]) : "r"(addr));
}
__device__ __forceinline__ void ldsm_x4t(uint32_t r[4], uint32_t addr) {
    asm volatile("ldmatrix.sync.aligned.m8n8.x4.trans.shared.b16 {%0,%1,%2,%3}, [%4];"
                 : "=r"(r[0]), "=r"(r[1]), "=r"(r[2]), "=r"(r[3]) : "r"(addr));
}
__device__ __forceinline__ void stsm_x4(uint32_t addr, const uint32_t r[4]) {
    asm volatile("stmatrix.sync.aligned.m8n8.x4.shared.b16 [%0], {%1,%2,%3,%4};"
                 :: "r"(addr), "r"(r[0]), "r"(r[1]), "r"(r[2]), "r"(r[3]) : "memory");
}
__device__ __forceinline__ void mma_f16(float d[4], const uint32_t a[4],
                                        uint32_t b0, uint32_t b1) {
    asm volatile("mma.sync.aligned.m16n8k16.row.col.f32.f16.f16.f32 "
                 "{%0,%1,%2,%3}, {%4,%5,%6,%7}, {%8,%9}, {%0,%1,%2,%3};"
                 : "+f"(d[0]), "+f"(d[1]), "+f"(d[2]), "+f"(d[3])
                 : "r"(a[0]), "r"(a[1]), "r"(a[2]), "r"(a[3]), "r"(b0), "r"(b1));
}
// 2-warp pair barrier (warps mb and mb+4), named barrier id = mb+1
#define BARP(id) asm volatile("bar.sync %0, 64;" :: "r"(id) : "memory")

__device__ __forceinline__ uint32_t pack_f16(float y0, float y1) {
    __half2 h = __floats2half2_rn(y0, y1);      // y0 in low half
    return *reinterpret_cast<uint32_t*>(&h);
}

// ---------------- K0: fold BN into weights, emit fp16 images -----------------
__global__ void fold_kernel(const float* __restrict__ W1, const float* __restrict__ W2,
                            const float* __restrict__ W3, const float* __restrict__ Wc1,
                            const float* __restrict__ Wc2,
                            const float* __restrict__ g1, const float* __restrict__ v1,
                            const float* __restrict__ g2, const float* __restrict__ b2,
                            const float* __restrict__ m2, const float* __restrict__ v2,
                            const float* __restrict__ g3, const float* __restrict__ b3,
                            const float* __restrict__ m3, const float* __restrict__ v3,
                            const float* __restrict__ gc1, const float* __restrict__ bc1,
                            const float* __restrict__ mc1, const float* __restrict__ vc1) {
    __shared__ float a2s[H_], a3s[H_], ac1s[H_];
    int tid = threadIdx.x;
    if (tid < H_) {
        float A1 = g1[tid] * rsqrtf(v1[tid] + 1e-5f);
        d_w0[tid] = A1 * W1[tid * (F_ + 1)];
        float A2 = g2[tid] * rsqrtf(v2[tid] + 1e-5f);
        a2s[tid] = A2;  d_b2v[tid] = b2[tid] - A2 * m2[tid];
        float A3 = g3[tid] * rsqrtf(v3[tid] + 1e-5f);
        a3s[tid] = A3;  d_b3v[tid] = b3[tid] - A3 * m3[tid];
        float Ac = gc1[tid] * rsqrtf(vc1[tid] + 1e-5f);
        ac1s[tid] = Ac; d_bc1v[tid] = bc1[tid] - Ac * mc1[tid];
    }
    __syncthreads();
    // image rows k = h (0..63), columns g
    for (int i = tid; i < 64 * 64; i += 256) {
        int k = i >> 6, g = i & 63;
        float w2v = a2s[g] * W2[g * H_ + k];
        float w3v = a3s[g] * W3[g * H_ + k];
        uint32_t off = (uint32_t)k * 128u + ((((uint32_t)g >> 3) ^ ((uint32_t)k & 7u)) << 4)
                       + (((uint32_t)g & 7u) << 1);
        d_W2img[off >> 1] = __half_as_ushort(__float2half_rn(w2v));
        d_W3img[off >> 1] = __half_as_ushort(__float2half_rn(w3v));
    }
    for (int i = tid; i < H_ * H_; i += 256) {
        int k = i >> 6, g = i & 63;
        d_Wc1t[k * H_ + g] = ac1s[g] * Wc1[g * H_ + k];
    }
    for (int i = tid; i < H_ * O_; i += 256) {
        int h = i >> 7, o = i & 127;
        d_Wc2t[h * O_ + o] = Wc2[o * H_ + h];
    }
}

// ---------------- K1: A' = BN1-folded W1[:,1:] @ t ---------------------------
__global__ void ap_kernel(const float* __restrict__ t, const float* __restrict__ W1,
                          const float* __restrict__ g1, const float* __restrict__ b1,
                          const float* __restrict__ m1, const float* __restrict__ v1) {
    int bh = blockIdx.x;
    int b = bh >> 6, h = bh & 63;
    int m = threadIdx.x;
    __shared__ float w[F_];
    if (m < F_) w[m] = W1[h * (F_ + 1) + 1 + m];
    __syncthreads();
    const float* tp = t + (size_t)b * F_ * M_ + m;
    float acc = 0.f;
#pragma unroll 8
    for (int f = 0; f < F_; f++) acc = fmaf(w[f], tp[f * M_], acc);
    float A1 = g1[h] * rsqrtf(v1[h] + 1e-5f);
    float B1 = b1[h] - A1 * m1[h];
    d_Ap[bh * M_ + m] = fmaf(A1, acc, B1);
}

// ---------------- K2: cosine-similarity GEMM + inline norms ------------------
__global__ void __launch_bounds__(256) cos_kernel(const float* __restrict__ t,
                                                  const float* __restrict__ s) {
    int b = blockIdx.z;
    int m0 = blockIdx.y * 64;
    int n0 = blockIdx.x * 64;
    __shared__ float ts[16][64];
    __shared__ float ss[16][64];
    __shared__ float ntp[4][64], nsp[4][64];
    __shared__ float nts[64], nss[64];
    int tid = threadIdx.x, ty = tid >> 4, tx = tid & 15;
    float acc[4][4] = {};
    float tss = 0.f, sss = 0.f;
    const float* tb = t + (size_t)b * F_ * M_;
    const float* sb = s + (size_t)b * F_ * N_;
    for (int f0 = 0; f0 < F_; f0 += 16) {
        __syncthreads();
#pragma unroll
        for (int i = 0; i < 4; i++) {
            int e = tid + i * 256;
            int fr = e >> 6, cc = e & 63;
            float tv = tb[(f0 + fr) * M_ + m0 + cc];
            float sv = sb[(f0 + fr) * N_ + n0 + cc];
            ts[fr][cc] = tv; tss = fmaf(tv, tv, tss);
            ss[fr][cc] = sv; sss = fmaf(sv, sv, sss);
        }
        __syncthreads();
#pragma unroll
        for (int k = 0; k < 16; k++) {
            float4 av = *(const float4*)&ts[k][4 * ty];
            float4 bv = *(const float4*)&ss[k][4 * tx];
            float a0 = av.x, a1 = av.y, a2 = av.z, a3 = av.w;
            float b0 = bv.x, b1 = bv.y, b2 = bv.z, b3 = bv.w;
            acc[0][0] = fmaf(a0, b0, acc[0][0]); acc[0][1] = fmaf(a0, b1, acc[0][1]);
            acc[0][2] = fmaf(a0, b2, acc[0][2]); acc[0][3] = fmaf(a0, b3, acc[0][3]);
            acc[1][0] = fmaf(a1, b0, acc[1][0]); acc[1][1] = fmaf(a1, b1, acc[1][1]);
            acc[1][2] = fmaf(a1, b2, acc[1][2]); acc[1][3] = fmaf(a1, b3, acc[1][3]);
            acc[2][0] = fmaf(a2, b0, acc[2][0]); acc[2][1] = fmaf(a2, b1, acc[2][1]);
            acc[2][2] = fmaf(a2, b2, acc[2][2]); acc[2][3] = fmaf(a2, b3, acc[2][3]);
            acc[3][0] = fmaf(a3, b0, acc[3][0]); acc[3][1] = fmaf(a3, b1, acc[3][1]);
            acc[3][2] = fmaf(a3, b2, acc[3][2]); acc[3][3] = fmaf(a3, b3, acc[3][3]);
        }
    }
    ntp[tid >> 6][tid & 63] = tss;
    nsp[tid >> 6][tid & 63] = sss;
    __syncthreads();
    if (tid < 64)
        nts[tid] = sqrtf(ntp[0][tid] + ntp[1][tid] + ntp[2][tid] + ntp[3][tid]);
    else if (tid < 128) {
        int c = tid - 64;
        nss[c] = sqrtf(nsp[0][c] + nsp[1][c] + nsp[2][c] + nsp[3][c]);
    }
    __syncthreads();
    float ntv[4], nsv[4];
#pragma unroll
    for (int r = 0; r < 4; r++) ntv[r] = nts[4 * ty + r];
#pragma unroll
    for (int c = 0; c < 4; c++) nsv[c] = nss[4 * tx + c];
#pragma unroll
    for (int c = 0; c < 4; c++) {
        int n = n0 + 4 * tx + c;
        float4 v;
        v.x = acc[0][c] / fmaxf(ntv[0] * nsv[c], 1e-8f);
        v.y = acc[1][c] / fmaxf(ntv[1] * nsv[c], 1e-8f);
        v.z = acc[2][c] / fmaxf(ntv[2] * nsv[c], 1e-8f);
        v.w = acc[3][c] / fmaxf(ntv[3] * nsv[c], 1e-8f);
        *(float4*)&d_cos[((size_t)b * N_ + n) * M_ + m0 + 4 * ty] = v;
    }
}

// ---------------- K3: fused MLP + maxpool + head (fp16, K=64) ----------------
// SMEM map (bytes):
//  0       W2 image (8192)
//  8192    W3 image (8192)
//  16384   X1 [128 m][144B] fp16 (18432)
//  34816   X2 [128 m][144B] fp16 (18432)
//  53248   aps [128 m][68 f] f32 (34816)
//  88064   red [8 nl][4 mb][64 g] f32 (8192)
//  96256   w0s (256) | 96512 b2s (256) | 96768 b3s (256)
#define XS1_OFF  16384
#define XS2_OFF  34816
#define AP_OFF   53248
#define RED_OFF  88064
#define W0_OFF   96256
#define B2_OFF   96512
#define B3_OFF   96768
#define MAIN_SMEM_BYTES 97024

// warp (gb,mb) computes [rows mb*32..+31] x [cols gb*32..+31], K=64 fp16
__device__ __forceinline__ void do_gemm(uint32_t xs_u32, uint32_t w_u32,
                                        int lane, int gb, int mb, float acc[2][4][4]) {
    uint32_t aaddr0 = xs_u32 + (uint32_t)((mb * 32 + (lane & 15)) * ROWB + ((lane >> 4) << 4));
    uint32_t aaddr1 = aaddr0 + 16 * ROWB;
    int kk = (lane & 7) + ((lane >> 3) & 1) * 8;
    int nc0 = gb * 4 + (lane >> 4);
    uint32_t baddr0 = w_u32 + (uint32_t)(kk * 128 + ((nc0 ^ (lane & 7)) << 4));
    uint32_t baddr1 = w_u32 + (uint32_t)(kk * 128 + (((nc0 + 2) ^ (lane & 7)) << 4));
#pragma unroll
    for (int k = 0; k < 4; k++) {
        uint32_t a0[4], a1[4], b0[4], b1[4];
        ldsm_x4 (a0, aaddr0 + k * 32);
        ldsm_x4 (a1, aaddr1 + k * 32);
        ldsm_x4t(b0, baddr0 + k * 2048);
        ldsm_x4t(b1, baddr1 + k * 2048);
        mma_f16(acc[0][0], a0, b0[0], b0[1]); mma_f16(acc[0][1], a0, b0[2], b0[3]);
        mma_f16(acc[0][2], a0, b1[0], b1[1]); mma_f16(acc[0][3], a0, b1[2], b1[3]);
        mma_f16(acc[1][0], a1, b0[0], b0[1]); mma_f16(acc[1][1], a1, b0[2], b0[3]);
        mma_f16(acc[1][2], a1, b1[0], b1[1]); mma_f16(acc[1][3], a1, b1[2], b1[3]);
    }
}

__global__ void __launch_bounds__(256, 2) main_kernel(const float* __restrict__ bc2,
                                                      float* __restrict__ out) {
    extern __shared__ char smem[];
    float* aps = (float*)(smem + AP_OFF);   // [m][68]
    float* red = (float*)(smem + RED_OFF);
    float* w0s = (float*)(smem + W0_OFF);
    float* b2s = (float*)(smem + B2_OFF);
    float* b3s = (float*)(smem + B3_OFF);

    uint32_t sb32 = smem_to_u32(smem);
    uint32_t x1_u32 = sb32 + XS1_OFF;
    uint32_t x2_u32 = sb32 + XS2_OFF;

    int tid = threadIdx.x;
    int wid = tid >> 5, lane = tid & 31;
    int gb = wid >> 2, mb = wid & 3;
    int barid = mb + 1;
    int b = blockIdx.y;
    int n0 = blockIdx.x * NPB;

    // stage weights + biases; init red
    {
        const uint4* sw2 = (const uint4*)d_W2img;
        const uint4* sw3 = (const uint4*)d_W3img;
        uint4* dw2 = (uint4*)smem;
        uint4* dw3 = (uint4*)(smem + 8192);
#pragma unroll
        for (int i = 0; i < 2; i++) {
            dw2[tid + i * 256] = sw2[tid + i * 256];
            dw3[tid + i * 256] = sw3[tid + i * 256];
        }
        if (tid < 64) {
            w0s[tid] = d_w0[tid];
            b2s[tid] = d_b2v[tid];
            b3s[tid] = d_b3v[tid];
        }
#pragma unroll
        for (int i = 0; i < 8; i++) red[tid + i * 256] = 0.f;
    }

    for (int mt = 0; mt < 2; mt++) {
        __syncthreads();   // all readers of aps/X from prev phase done
        // stage Ap transposed into aps[m][68]: float4-coalesced over m, scatter
#pragma unroll
        for (int i = 0; i < 8; i++) {
            int e = tid + i * 256;           // 0..2047
            int h = e >> 5, q = e & 31;
            float4 v = *(const float4*)(d_Ap + ((size_t)b * H_ + h) * M_ + mt * 128 + 4 * q);
            aps[(4 * q + 0) * 68 + h] = v.x;
            aps[(4 * q + 1) * 68 + h] = v.y;
            aps[(4 * q + 2) * 68 + h] = v.z;
            aps[(4 * q + 3) * 68 + h] = v.w;
        }
        __syncthreads();

        for (int nl = 0; nl < NPB; nl++) {
            // ---- build X1 (pair-closed rows): thread -> row m = tid&127 ----
            {
                int m = tid & 127;
                int hb = (tid >> 7) * 32;
                float cv = __ldg(d_cos + ((size_t)b * N_ + n0 + nl) * M_ + mt * 128 + m);
                char* row = smem + XS1_OFF + m * ROWB;
                const float* ar = aps + m * 68 + hb;
#pragma unroll
                for (int cc = 0; cc < 4; cc++) {
                    int h0 = hb + 8 * cc;
                    float4 a0 = *(const float4*)(ar + 8 * cc);
                    float4 a1 = *(const float4*)(ar + 8 * cc + 4);
                    float y0 = fmaxf(fmaf(w0s[h0 + 0], cv, a0.x), 0.f);
                    float y1 = fmaxf(fmaf(w0s[h0 + 1], cv, a0.y), 0.f);
                    float y2 = fmaxf(fmaf(w0s[h0 + 2], cv, a0.z), 0.f);
                    float y3 = fmaxf(fmaf(w0s[h0 + 3], cv, a0.w), 0.f);
                    float y4 = fmaxf(fmaf(w0s[h0 + 4], cv, a1.x), 0.f);
                    float y5 = fmaxf(fmaf(w0s[h0 + 5], cv, a1.y), 0.f);
                    float y6 = fmaxf(fmaf(w0s[h0 + 6], cv, a1.z), 0.f);
                    float y7 = fmaxf(fmaf(w0s[h0 + 7], cv, a1.w), 0.f);
                    uint4 hh;
                    hh.x = pack_f16(y0, y1);
                    hh.y = pack_f16(y2, y3);
                    hh.z = pack_f16(y4, y5);
                    hh.w = pack_f16(y6, y7);
                    *(uint4*)(row + h0 * 2) = hh;
                }
            }
            BARP(barid);   // pair's X1 complete; pair's G1(prev) done implies safety

            // ---- GEMM1: W2f @ X1 ----
            float acc[2][4][4] = {};
            do_gemm(x1_u32, sb32, lane, gb, mb, acc);

            // ---- epilogue 1: relu(+b2), pack fp16, stmatrix into X2 ----
            {
                int j = lane >> 3, r = lane & 7;
                int g0 = gb * 32 + 2 * (lane & 3);
                uint32_t adbase = x2_u32
                    + (uint32_t)((mb * 32 + (j & 1) * 8 + r) * ROWB + gb * 64 + (j >> 1) * 16);
#pragma unroll
                for (int i = 0; i < 2; i++) {
#pragma unroll
                    for (int tp = 0; tp < 2; tp++) {
                        int t0 = 2 * tp, t1 = t0 + 1;
                        float b00 = b2s[g0 + 8 * t0], b01 = b2s[g0 + 8 * t0 + 1];
                        float b10 = b2s[g0 + 8 * t1], b11 = b2s[g0 + 8 * t1 + 1];
                        uint32_t hh[4];
                        hh[0] = pack_f16(fmaxf(acc[i][t0][0] + b00, 0.f),
                                         fmaxf(acc[i][t0][1] + b01, 0.f));
                        hh[1] = pack_f16(fmaxf(acc[i][t0][2] + b00, 0.f),
                                         fmaxf(acc[i][t0][3] + b01, 0.f));
                        hh[2] = pack_f16(fmaxf(acc[i][t1][0] + b10, 0.f),
                                         fmaxf(acc[i][t1][1] + b11, 0.f));
                        hh[3] = pack_f16(fmaxf(acc[i][t1][2] + b10, 0.f),
                                         fmaxf(acc[i][t1][3] + b11, 0.f));
                        stsm_x4(adbase + (uint32_t)(i * 16 * ROWB + t0 * 16), hh);
                    }
                }
            }
            BARP(barid);   // pair's X2 complete

            // ---- GEMM2: W3f @ X2 ----
            float acc2[2][4][4] = {};
            do_gemm(x2_u32, sb32 + 8192, lane, gb, mb, acc2);

            // ---- epilogue 2: relu(+b3), max over m -> red RMW (race-free) ----
            {
                int g0 = gb * 32 + 2 * (lane & 3);
#pragma unroll
                for (int t = 0; t < 4; t++) {
#pragma unroll
                    for (int d = 0; d < 2; d++) {
                        int gg = g0 + d + 8 * t;
                        float v = fmaxf(fmaxf(acc2[0][t][d], acc2[0][t][2 + d]),
                                        fmaxf(acc2[1][t][d], acc2[1][t][2 + d]));
                        v = fmaxf(v + b3s[gg], 0.f);
                        v = fmaxf(v, __shfl_xor_sync(0xFFFFFFFFu, v, 4));
                        v = fmaxf(v, __shfl_xor_sync(0xFFFFFFFFu, v, 8));
                        v = fmaxf(v, __shfl_xor_sync(0xFFFFFFFFu, v, 16));
                        if (lane < 4) {
                            int ri = nl * 256 + mb * 64 + gg;
                            red[ri] = fmaxf(red[ri], v);
                        }
                    }
                }
            }
            // no barrier: next build writes X1; pair's G1 finished before bar2.
        }
    }

    // ---- fused head: pool -> c = relu(Wc1f p + bc1) -> out = Wc2 c + bc2 ----
    __syncthreads();
    float* ps = aps;                       // reuse [512] floats
    float* cs = (float*)(smem + XS1_OFF);  // reuse [512] floats
#pragma unroll
    for (int i = 0; i < 2; i++) {
        int e = tid + i * 256;
        int nl = e >> 6, h = e & 63;
        const float* r = red + nl * 256;
        ps[e] = fmaxf(fmaxf(r[h], r[64 + h]), fmaxf(r[128 + h], r[192 + h]));
    }
    __syncthreads();
#pragma unroll
    for (int i = 0; i < 2; i++) {
        int e = tid + i * 256;
        int nl = e >> 6, g = e & 63;
        float acc = d_bc1v[g];
        const float* pv = ps + nl * 64;
#pragma unroll 16
        for (int h = 0; h < 64; h++) acc = fmaf(__ldg(d_Wc1t + h * 64 + g), pv[h], acc);
        cs[e] = fmaxf(acc, 0.f);
    }
    __syncthreads();
#pragma unroll
    for (int i = 0; i < 4; i++) {
        int e = tid + i * 256;
        int nl = e >> 7, o = e & 127;
        float acc = __ldg(bc2 + o);
        const float* cv = cs + nl * 64;
#pragma unroll 16
        for (int h = 0; h < 64; h++) acc = fmaf(__ldg(d_Wc2t + h * 128 + o), cv[h], acc);
        out[((size_t)b * O_ + o) * N_ + n0 + nl] = acc;
    }
}

// ---------------- launch ------------------------------------------------------
extern "C" void kernel_launch(void* const* d_in, const int* in_sizes, int n_in,
                              void* d_out, int out_size) {
    const float* t   = (const float*)d_in[0];
    const float* s   = (const float*)d_in[1];
    const float* W1  = (const float*)d_in[2];
    const float* W2  = (const float*)d_in[3];
    const float* W3  = (const float*)d_in[4];
    const float* Wc1 = (const float*)d_in[5];
    const float* Wc2 = (const float*)d_in[6];
    const float* bc2 = (const float*)d_in[7];
    const float* g1 = (const float*)d_in[8],  *b1 = (const float*)d_in[9];
    const float* m1 = (const float*)d_in[10], *v1 = (const float*)d_in[11];
    const float* g2 = (const float*)d_in[12], *b2 = (const float*)d_in[13];
    const float* m2 = (const float*)d_in[14], *v2 = (const float*)d_in[15];
    const float* g3 = (const float*)d_in[16], *b3 = (const float*)d_in[17];
    const float* m3 = (const float*)d_in[18], *v3 = (const float*)d_in[19];
    const float* gc1 = (const float*)d_in[20], *bc1 = (const float*)d_in[21];
    const float* mc1 = (const float*)d_in[22], *vc1 = (const float*)d_in[23];
    float* out = (float*)d_out;

    cudaFuncSetAttribute(main_kernel, cudaFuncAttributeMaxDynamicSharedMemorySize,
                         MAIN_SMEM_BYTES);

    fold_kernel<<<1, 256>>>(W1, W2, W3, Wc1, Wc2, g1, v1,
                            g2, b2, m2, v2, g3, b3, m3, v3, gc1, bc1, mc1, vc1);
    ap_kernel<<<B_ * H_, 256>>>(t, W1, g1, b1, m1, v1);
    cos_kernel<<<dim3(N_ / 64, M_ / 64, B_), 256>>>(t, s);
    main_kernel<<<dim3(N_ / NPB, B_), 256, MAIN_SMEM_BYTES>>>(bc2, out);
}

// round 16
// speedup vs baseline: 2.0653x; 1.0746x over previous
#include <cuda_runtime.h>
#include <cuda_bf16.h>
#include <cuda_fp16.h>
#include <cstdint>

#define B_ 8
#define F_ 128
#define M_ 256
#define N_ 1024
#define H_ 64
#define O_ 128
#define NPB 8
#define ROWB 144   // X row bytes: 128 fp16 + 16 pad; aps row bytes: 72 halves = 144

// ---------------- scratch (device globals; no allocations allowed) ----------
__device__ __align__(16) float d_cos[B_ * N_ * M_];   // [b][n][m]
__device__ __align__(16) float d_Ap [B_ * H_ * M_];   // [b][h][m]
__device__ float d_w0 [H_];
__device__ float d_b2v[H_], d_b3v[H_], d_bc1v[H_];
// fp16 weight images [k=64 rows][64 g], 128B rows, 16B-chunk XOR swizzle
__device__ __align__(16) unsigned short d_W2img[64 * 64];
__device__ __align__(16) unsigned short d_W3img[64 * 64];
__device__ __align__(16) float d_Wc1t[H_ * H_];   // [h][g], BNc1-folded
__device__ __align__(16) float d_Wc2t[H_ * O_];   // [h][o]

// ================= tensor-core helpers (sm_80/90 PTX, valid on sm_103) ======
__device__ __forceinline__ uint32_t smem_to_u32(const void* p) {
    uint32_t a;
    asm("{ .reg .u64 t; cvta.to.shared.u64 t, %1; cvt.u32.u64 %0, t; }" : "=r"(a) : "l"(p));
    return a;
}
__device__ __forceinline__ void ldsm_x4(uint32_t r[4], uint32_t addr) {
    asm volatile("ldmatrix.sync.aligned.m8n8.x4.shared.b16 {%0,%1,%2,%3}, [%4];"
                 : "=r"(r[0]), "=r"(r[1]), "=r"(r[2]), "=r"(r[3]) : "r"(addr));
}
__device__ __forceinline__ void ldsm_x4t(uint32_t r[4], uint32_t addr) {
    asm volatile("ldmatrix.sync.aligned.m8n8.x4.trans.shared.b16 {%0,%1,%2,%3}, [%4];"
                 : "=r"(r[0]), "=r"(r[1]), "=r"(r[2]), "=r"(r[3]) : "r"(addr));
}
__device__ __forceinline__ void stsm_x4(uint32_t addr, const uint32_t r[4]) {
    asm volatile("stmatrix.sync.aligned.m8n8.x4.shared.b16 [%0], {%1,%2,%3,%4};"
                 :: "r"(addr), "r"(r[0]), "r"(r[1]), "r"(r[2]), "r"(r[3]) : "memory");
}
__device__ __forceinline__ void mma_f16(float d[4], const uint32_t a[4],
                                        uint32_t b0, uint32_t b1) {
    asm volatile("mma.sync.aligned.m16n8k16.row.col.f32.f16.f16.f32 "
                 "{%0,%1,%2,%3}, {%4,%5,%6,%7}, {%8,%9}, {%0,%1,%2,%3};"
                 : "+f"(d[0]), "+f"(d[1]), "+f"(d[2]), "+f"(d[3])
                 : "r"(a[0]), "r"(a[1]), "r"(a[2]), "r"(a[3]), "r"(b0), "r"(b1));
}
// 2-warp pair barrier (warps mb and mb+4), named barrier id = mb+1
#define BARP(id) asm volatile("bar.sync %0, 64;" :: "r"(id) : "memory")

__device__ __forceinline__ uint32_t pack_f16(float y0, float y1) {
    __half2 h = __floats2half2_rn(y0, y1);      // y0 in low half
    return *reinterpret_cast<uint32_t*>(&h);
}

// ---------------- K0: fold BN into weights, emit fp16 images -----------------
__global__ void fold_kernel(const float* __restrict__ W1, const float* __restrict__ W2,
                            const float* __restrict__ W3, const float* __restrict__ Wc1,
                            const float* __restrict__ Wc2,
                            const float* __restrict__ g1, const float* __restrict__ v1,
                            const float* __restrict__ g2, const float* __restrict__ b2,
                            const float* __restrict__ m2, const float* __restrict__ v2,
                            const float* __restrict__ g3, const float* __restrict__ b3,
                            const float* __restrict__ m3, const float* __restrict__ v3,
                            const float* __restrict__ gc1, const float* __restrict__ bc1,
                            const float* __restrict__ mc1, const float* __restrict__ vc1) {
    __shared__ float a2s[H_], a3s[H_], ac1s[H_];
    int tid = threadIdx.x;
    if (tid < H_) {
        float A1 = g1[tid] * rsqrtf(v1[tid] + 1e-5f);
        d_w0[tid] = A1 * W1[tid * (F_ + 1)];
        float A2 = g2[tid] * rsqrtf(v2[tid] + 1e-5f);
        a2s[tid] = A2;  d_b2v[tid] = b2[tid] - A2 * m2[tid];
        float A3 = g3[tid] * rsqrtf(v3[tid] + 1e-5f);
        a3s[tid] = A3;  d_b3v[tid] = b3[tid] - A3 * m3[tid];
        float Ac = gc1[tid] * rsqrtf(vc1[tid] + 1e-5f);
        ac1s[tid] = Ac; d_bc1v[tid] = bc1[tid] - Ac * mc1[tid];
    }
    __syncthreads();
    for (int i = tid; i < 64 * 64; i += 256) {
        int k = i >> 6, g = i & 63;
        float w2v = a2s[g] * W2[g * H_ + k];
        float w3v = a3s[g] * W3[g * H_ + k];
        uint32_t off = (uint32_t)k * 128u + ((((uint32_t)g >> 3) ^ ((uint32_t)k & 7u)) << 4)
                       + (((uint32_t)g & 7u) << 1);
        d_W2img[off >> 1] = __half_as_ushort(__float2half_rn(w2v));
        d_W3img[off >> 1] = __half_as_ushort(__float2half_rn(w3v));
    }
    for (int i = tid; i < H_ * H_; i += 256) {
        int k = i >> 6, g = i & 63;
        d_Wc1t[k * H_ + g] = ac1s[g] * Wc1[g * H_ + k];
    }
    for (int i = tid; i < H_ * O_; i += 256) {
        int h = i >> 7, o = i & 127;
        d_Wc2t[h * O_ + o] = Wc2[o * H_ + h];
    }
}

// ---------------- K1: A' = BN1-folded W1[:,1:] @ t ---------------------------
__global__ void ap_kernel(const float* __restrict__ t, const float* __restrict__ W1,
                          const float* __restrict__ g1, const float* __restrict__ b1,
                          const float* __restrict__ m1, const float* __restrict__ v1) {
    int bh = blockIdx.x;
    int b = bh >> 6, h = bh & 63;
    int m = threadIdx.x;
    __shared__ float w[F_];
    if (m < F_) w[m] = W1[h * (F_ + 1) + 1 + m];
    __syncthreads();
    const float* tp = t + (size_t)b * F_ * M_ + m;
    float acc = 0.f;
#pragma unroll 8
    for (int f = 0; f < F_; f++) acc = fmaf(w[f], tp[f * M_], acc);
    float A1 = g1[h] * rsqrtf(v1[h] + 1e-5f);
    float B1 = b1[h] - A1 * m1[h];
    d_Ap[bh * M_ + m] = fmaf(A1, acc, B1);
}

// ---------------- K2: cosine-similarity GEMM + inline norms ------------------
__global__ void __launch_bounds__(256) cos_kernel(const float* __restrict__ t,
                                                  const float* __restrict__ s) {
    int b = blockIdx.z;
    int m0 = blockIdx.y * 64;
    int n0 = blockIdx.x * 64;
    __shared__ float ts[16][64];
    __shared__ float ss[16][64];
    __shared__ float ntp[4][64], nsp[4][64];
    __shared__ float nts[64], nss[64];
    int tid = threadIdx.x, ty = tid >> 4, tx = tid & 15;
    float acc[4][4] = {};
    float tss = 0.f, sss = 0.f;
    const float* tb = t + (size_t)b * F_ * M_;
    const float* sb = s + (size_t)b * F_ * N_;
    for (int f0 = 0; f0 < F_; f0 += 16) {
        __syncthreads();
#pragma unroll
        for (int i = 0; i < 4; i++) {
            int e = tid + i * 256;
            int fr = e >> 6, cc = e & 63;
            float tv = tb[(f0 + fr) * M_ + m0 + cc];
            float sv = sb[(f0 + fr) * N_ + n0 + cc];
            ts[fr][cc] = tv; tss = fmaf(tv, tv, tss);
            ss[fr][cc] = sv; sss = fmaf(sv, sv, sss);
        }
        __syncthreads();
#pragma unroll
        for (int k = 0; k < 16; k++) {
            float4 av = *(const float4*)&ts[k][4 * ty];
            float4 bv = *(const float4*)&ss[k][4 * tx];
            float a0 = av.x, a1 = av.y, a2 = av.z, a3 = av.w;
            float b0 = bv.x, b1 = bv.y, b2 = bv.z, b3 = bv.w;
            acc[0][0] = fmaf(a0, b0, acc[0][0]); acc[0][1] = fmaf(a0, b1, acc[0][1]);
            acc[0][2] = fmaf(a0, b2, acc[0][2]); acc[0][3] = fmaf(a0, b3, acc[0][3]);
            acc[1][0] = fmaf(a1, b0, acc[1][0]); acc[1][1] = fmaf(a1, b1, acc[1][1]);
            acc[1][2] = fmaf(a1, b2, acc[1][2]); acc[1][3] = fmaf(a1, b3, acc[1][3]);
            acc[2][0] = fmaf(a2, b0, acc[2][0]); acc[2][1] = fmaf(a2, b1, acc[2][1]);
            acc[2][2] = fmaf(a2, b2, acc[2][2]); acc[2][3] = fmaf(a2, b3, acc[2][3]);
            acc[3][0] = fmaf(a3, b0, acc[3][0]); acc[3][1] = fmaf(a3, b1, acc[3][1]);
            acc[3][2] = fmaf(a3, b2, acc[3][2]); acc[3][3] = fmaf(a3, b3, acc[3][3]);
        }
    }
    ntp[tid >> 6][tid & 63] = tss;
    nsp[tid >> 6][tid & 63] = sss;
    __syncthreads();
    if (tid < 64)
        nts[tid] = sqrtf(ntp[0][tid] + ntp[1][tid] + ntp[2][tid] + ntp[3][tid]);
    else if (tid < 128) {
        int c = tid - 64;
        nss[c] = sqrtf(nsp[0][c] + nsp[1][c] + nsp[2][c] + nsp[3][c]);
    }
    __syncthreads();
    float ntv[4], nsv[4];
#pragma unroll
    for (int r = 0; r < 4; r++) ntv[r] = nts[4 * ty + r];
#pragma unroll
    for (int c = 0; c < 4; c++) nsv[c] = nss[4 * tx + c];
#pragma unroll
    for (int c = 0; c < 4; c++) {
        int n = n0 + 4 * tx + c;
        float4 v;
        v.x = acc[0][c] / fmaxf(ntv[0] * nsv[c], 1e-8f);
        v.y = acc[1][c] / fmaxf(ntv[1] * nsv[c], 1e-8f);
        v.z = acc[2][c] / fmaxf(ntv[2] * nsv[c], 1e-8f);
        v.w = acc[3][c] / fmaxf(ntv[3] * nsv[c], 1e-8f);
        *(float4*)&d_cos[((size_t)b * N_ + n) * M_ + m0 + 4 * ty] = v;
    }
}

// ---------------- K3: fused MLP + maxpool + head (fp16, K=64, 3 blk/SM) ------
// SMEM map (bytes):
//  0       W2 image (8192)
//  8192    W3 image (8192)
//  16384   Xs [128 m][144B] fp16 (18432)
//  34816   aps fp16 [128 m][72 h] (18432)
//  53248   red [8 nl][4 mb][64 g] f32 (8192)
//  61440   w0s (256) | 61696 b2s (256) | 61952 b3s (256)
#define XS_OFF   16384
#define AP_OFF   34816
#define RED_OFF  53248
#define W0_OFF   61440
#define B2_OFF   61696
#define B3_OFF   61952
#define MAIN_SMEM_BYTES 62208

// warp (gb,mb) computes [rows mb*32..+31] x [cols gb*32..+31], K=64 fp16
__device__ __forceinline__ void do_gemm(uint32_t xs_u32, uint32_t w_u32,
                                        int lane, int gb, int mb, float acc[2][4][4]) {
    uint32_t aaddr0 = xs_u32 + (uint32_t)((mb * 32 + (lane & 15)) * ROWB + ((lane >> 4) << 4));
    uint32_t aaddr1 = aaddr0 + 16 * ROWB;
    int kk = (lane & 7) + ((lane >> 3) & 1) * 8;
    int nc0 = gb * 4 + (lane >> 4);
    uint32_t baddr0 = w_u32 + (uint32_t)(kk * 128 + ((nc0 ^ (lane & 7)) << 4));
    uint32_t baddr1 = w_u32 + (uint32_t)(kk * 128 + (((nc0 + 2) ^ (lane & 7)) << 4));
#pragma unroll
    for (int k = 0; k < 4; k++) {
        uint32_t a0[4], a1[4], b0[4], b1[4];
        ldsm_x4 (a0, aaddr0 + k * 32);
        ldsm_x4 (a1, aaddr1 + k * 32);
        ldsm_x4t(b0, baddr0 + k * 2048);
        ldsm_x4t(b1, baddr1 + k * 2048);
        mma_f16(acc[0][0], a0, b0[0], b0[1]); mma_f16(acc[0][1], a0, b0[2], b0[3]);
        mma_f16(acc[0][2], a0, b1[0], b1[1]); mma_f16(acc[0][3], a0, b1[2], b1[3]);
        mma_f16(acc[1][0], a1, b0[0], b0[1]); mma_f16(acc[1][1], a1, b0[2], b0[3]);
        mma_f16(acc[1][2], a1, b1[0], b1[1]); mma_f16(acc[1][3], a1, b1[2], b1[3]);
    }
}

__global__ void __launch_bounds__(256, 3) main_kernel(const float* __restrict__ bc2,
                                                      float* __restrict__ out) {
    extern __shared__ char smem[];
    __half* apsh = (__half*)(smem + AP_OFF);   // [m][72]
    float* red = (float*)(smem + RED_OFF);
    float* w0s = (float*)(smem + W0_OFF);
    float* b2s = (float*)(smem + B2_OFF);
    float* b3s = (float*)(smem + B3_OFF);

    uint32_t sb32 = smem_to_u32(smem);
    uint32_t xs_u32 = sb32 + XS_OFF;

    int tid = threadIdx.x;
    int wid = tid >> 5, lane = tid & 31;
    int gb = wid >> 2, mb = wid & 3;
    int barid = mb + 1;
    int b = blockIdx.y;
    int n0 = blockIdx.x * NPB;

    // stage weights + biases; init red
    {
        const uint4* sw2 = (const uint4*)d_W2img;
        const uint4* sw3 = (const uint4*)d_W3img;
        uint4* dw2 = (uint4*)smem;
        uint4* dw3 = (uint4*)(smem + 8192);
#pragma unroll
        for (int i = 0; i < 2; i++) {
            dw2[tid + i * 256] = sw2[tid + i * 256];
            dw3[tid + i * 256] = sw3[tid + i * 256];
        }
        if (tid < 64) {
            w0s[tid] = d_w0[tid];
            b2s[tid] = d_b2v[tid];
            b3s[tid] = d_b3v[tid];
        }
#pragma unroll
        for (int i = 0; i < 8; i++) red[tid + i * 256] = 0.f;
    }

    for (int mt = 0; mt < 2; mt++) {
        __syncthreads();   // all readers of aps/Xs from prev phase done
        // stage Ap (fp16, transposed [m][72]): float4-coalesced over m, scatter
#pragma unroll
        for (int i = 0; i < 8; i++) {
            int e = tid + i * 256;           // 0..2047
            int h = e >> 5, q = e & 31;
            float4 v = *(const float4*)(d_Ap + ((size_t)b * H_ + h) * M_ + mt * 128 + 4 * q);
            apsh[(4 * q + 0) * 72 + h] = __float2half_rn(v.x);
            apsh[(4 * q + 1) * 72 + h] = __float2half_rn(v.y);
            apsh[(4 * q + 2) * 72 + h] = __float2half_rn(v.z);
            apsh[(4 * q + 3) * 72 + h] = __float2half_rn(v.w);
        }
        __syncthreads();

        for (int nl = 0; nl < NPB; nl++) {
            // ---- build X1 (pair-closed rows): thread -> row m = tid&127 ----
            {
                int m = tid & 127;
                int hb = (tid >> 7) * 32;
                float cv = __ldg(d_cos + ((size_t)b * N_ + n0 + nl) * M_ + mt * 128 + m);
                char* row = smem + XS_OFF + m * ROWB;
                const uint4* ar = (const uint4*)(smem + AP_OFF + m * 144 + hb * 2);
#pragma unroll
                for (int cc = 0; cc < 4; cc++) {
                    int h0 = hb + 8 * cc;
                    uint4 pk = ar[cc];
                    float2 f0 = __half22float2(*(__half2*)&pk.x);
                    float2 f1 = __half22float2(*(__half2*)&pk.y);
                    float2 f2 = __half22float2(*(__half2*)&pk.z);
                    float2 f3 = __half22float2(*(__half2*)&pk.w);
                    float y0 = fmaxf(fmaf(w0s[h0 + 0], cv, f0.x), 0.f);
                    float y1 = fmaxf(fmaf(w0s[h0 + 1], cv, f0.y), 0.f);
                    float y2 = fmaxf(fmaf(w0s[h0 + 2], cv, f1.x), 0.f);
                    float y3 = fmaxf(fmaf(w0s[h0 + 3], cv, f1.y), 0.f);
                    float y4 = fmaxf(fmaf(w0s[h0 + 4], cv, f2.x), 0.f);
                    float y5 = fmaxf(fmaf(w0s[h0 + 5], cv, f2.y), 0.f);
                    float y6 = fmaxf(fmaf(w0s[h0 + 6], cv, f3.x), 0.f);
                    float y7 = fmaxf(fmaf(w0s[h0 + 7], cv, f3.y), 0.f);
                    uint4 hh;
                    hh.x = pack_f16(y0, y1);
                    hh.y = pack_f16(y2, y3);
                    hh.z = pack_f16(y4, y5);
                    hh.w = pack_f16(y6, y7);
                    *(uint4*)(row + h0 * 2) = hh;
                }
            }
            BARP(barid);

            // ---- GEMM1: W2f @ X1 ----
            float acc[2][4][4] = {};
            do_gemm(xs_u32, sb32, lane, gb, mb, acc);
            BARP(barid);   // pair done reading rows mb before overwrite

            // ---- epilogue 1: relu(+b2), pack fp16, stmatrix in place ----
            {
                int j = lane >> 3, r = lane & 7;
                int g0 = gb * 32 + 2 * (lane & 3);
                uint32_t adbase = xs_u32
                    + (uint32_t)((mb * 32 + (j & 1) * 8 + r) * ROWB + gb * 64 + (j >> 1) * 16);
#pragma unroll
                for (int i = 0; i < 2; i++) {
#pragma unroll
                    for (int tp = 0; tp < 2; tp++) {
                        int t0 = 2 * tp, t1 = t0 + 1;
                        float b00 = b2s[g0 + 8 * t0], b01 = b2s[g0 + 8 * t0 + 1];
                        float b10 = b2s[g0 + 8 * t1], b11 = b2s[g0 + 8 * t1 + 1];
                        uint32_t hh[4];
                        hh[0] = pack_f16(fmaxf(acc[i][t0][0] + b00, 0.f),
                                         fmaxf(acc[i][t0][1] + b01, 0.f));
                        hh[1] = pack_f16(fmaxf(acc[i][t0][2] + b00, 0.f),
                                         fmaxf(acc[i][t0][3] + b01, 0.f));
                        hh[2] = pack_f16(fmaxf(acc[i][t1][0] + b10, 0.f),
                                         fmaxf(acc[i][t1][1] + b11, 0.f));
                        hh[3] = pack_f16(fmaxf(acc[i][t1][2] + b10, 0.f),
                                         fmaxf(acc[i][t1][3] + b11, 0.f));
                        stsm_x4(adbase + (uint32_t)(i * 16 * ROWB + t0 * 16), hh);
                    }
                }
            }
            BARP(barid);

            // ---- GEMM2: W3f @ X2 ----
            float acc2[2][4][4] = {};
            do_gemm(xs_u32, sb32 + 8192, lane, gb, mb, acc2);

            // ---- epilogue 2: relu(+b3), max over m -> red RMW (race-free) ----
            {
                int g0 = gb * 32 + 2 * (lane & 3);
#pragma unroll
                for (int t = 0; t < 4; t++) {
#pragma unroll
                    for (int d = 0; d < 2; d++) {
                        int gg = g0 + d + 8 * t;
                        float v = fmaxf(fmaxf(acc2[0][t][d], acc2[0][t][2 + d]),
                                        fmaxf(acc2[1][t][d], acc2[1][t][2 + d]));
                        v = fmaxf(v + b3s[gg], 0.f);
                        v = fmaxf(v, __shfl_xor_sync(0xFFFFFFFFu, v, 4));
                        v = fmaxf(v, __shfl_xor_sync(0xFFFFFFFFu, v, 8));
                        v = fmaxf(v, __shfl_xor_sync(0xFFFFFFFFu, v, 16));
                        if (lane < 4) {
                            int ri = nl * 256 + mb * 64 + gg;
                            red[ri] = fmaxf(red[ri], v);
                        }
                    }
                }
            }
            BARP(barid);   // pair done reading rows mb before next build
        }
    }

    // ---- fused head: pool -> c = relu(Wc1f p + bc1) -> out = Wc2 c + bc2 ----
    __syncthreads();
    float* ps = (float*)(smem + AP_OFF);   // reuse (512 floats)
    float* cs = (float*)(smem + XS_OFF);   // reuse (512 floats)
#pragma unroll
    for (int i = 0; i < 2; i++) {
        int e = tid + i * 256;
        int nl = e >> 6, h = e & 63;
        const float* r = red + nl * 256;
        ps[e] = fmaxf(fmaxf(r[h], r[64 + h]), fmaxf(r[128 + h], r[192 + h]));
    }
    __syncthreads();
#pragma unroll
    for (int i = 0; i < 2; i++) {
        int e = tid + i * 256;
        int nl = e >> 6, g = e & 63;
        float acc = d_bc1v[g];
        const float* pv = ps + nl * 64;
#pragma unroll 16
        for (int h = 0; h < 64; h++) acc = fmaf(__ldg(d_Wc1t + h * 64 + g), pv[h], acc);
        cs[e] = fmaxf(acc, 0.f);
    }
    __syncthreads();
#pragma unroll
    for (int i = 0; i < 4; i++) {
        int e = tid + i * 256;
        int nl = e >> 7, o = e & 127;
        float acc = __ldg(bc2 + o);
        const float* cv = cs + nl * 64;
#pragma unroll 16
        for (int h = 0; h < 64; h++) acc = fmaf(__ldg(d_Wc2t + h * 128 + o), cv[h], acc);
        out[((size_t)b * O_ + o) * N_ + n0 + nl] = acc;
    }
}

// ---------------- launch ------------------------------------------------------
extern "C" void kernel_launch(void* const* d_in, const int* in_sizes, int n_in,
                              void* d_out, int out_size) {
    const float* t   = (const float*)d_in[0];
    const float* s   = (const float*)d_in[1];
    const float* W1  = (const float*)d_in[2];
    const float* W2  = (const float*)d_in[3];
    const float* W3  = (const float*)d_in[4];
    const float* Wc1 = (const float*)d_in[5];
    const float* Wc2 = (const float*)d_in[6];
    const float* bc2 = (const float*)d_in[7];
    const float* g1 = (const float*)d_in[8],  *b1 = (const float*)d_in[9];
    const float* m1 = (const float*)d_in[10], *v1 = (const float*)d_in[11];
    const float* g2 = (const float*)d_in[12], *b2 = (const float*)d_in[13];
    const float* m2 = (const float*)d_in[14], *v2 = (const float*)d_in[15];
    const float* g3 = (const float*)d_in[16], *b3 = (const float*)d_in[17];
    const float* m3 = (const float*)d_in[18], *v3 = (const float*)d_in[19];
    const float* gc1 = (const float*)d_in[20], *bc1 = (const float*)d_in[21];
    const float* mc1 = (const float*)d_in[22], *vc1 = (const float*)d_in[23];
    float* out = (float*)d_out;

    cudaFuncSetAttribute(main_kernel, cudaFuncAttributeMaxDynamicSharedMemorySize,
                         MAIN_SMEM_BYTES);

    fold_kernel<<<1, 256>>>(W1, W2, W3, Wc1, Wc2, g1, v1,
                            g2, b2, m2, v2, g3, b3, m3, v3, gc1, bc1, mc1, vc1);
    ap_kernel<<<B_ * H_, 256>>>(t, W1, g1, b1, m1, v1);
    cos_kernel<<<dim3(N_ / 64, M_ / 64, B_), 256>>>(t, s);
    main_kernel<<<dim3(N_ / NPB, B_), 256, MAIN_SMEM_BYTES>>>(bc2, out);
}

// round 17
// speedup vs baseline: 2.4302x; 1.1767x over previous
#include <cuda_runtime.h>
#include <cuda_bf16.h>
#include <cuda_fp16.h>
#include <cstdint>

#define B_ 8
#define F_ 128
#define M_ 256
#define N_ 1024
#define H_ 64
#define O_ 128
#define NPB 8
#define ROWB 144   // X2 row bytes: 128 fp16 + 16 pad; aps_f lane stride = 144 B

// ---------------- scratch (device globals; no allocations allowed) ----------
__device__ __align__(16) float d_cos[B_ * N_ * M_];   // [b][n][m]
__device__ __align__(16) float d_Ap [B_ * H_ * M_];   // [b][h][m]
__device__ float d_w0 [H_];
__device__ float d_b2v[H_], d_b3v[H_], d_bc1v[H_];
// fp16 weight images [k=64 rows][64 g], 128B rows, 16B-chunk XOR swizzle
__device__ __align__(16) unsigned short d_W2img[64 * 64];
__device__ __align__(16) unsigned short d_W3img[64 * 64];
__device__ __align__(16) float d_Wc1t[H_ * H_];   // [h][g], BNc1-folded
__device__ __align__(16) float d_Wc2t[H_ * O_];   // [h][o]

// ================= tensor-core helpers (sm_80/90 PTX, valid on sm_103) ======
__device__ __forceinline__ uint32_t smem_to_u32(const void* p) {
    uint32_t a;
    asm("{ .reg .u64 t; cvta.to.shared.u64 t, %1; cvt.u32.u64 %0, t; }" : "=r"(a) : "l"(p));
    return a;
}
__device__ __forceinline__ void ldsm_x4(uint32_t r[4], uint32_t addr) {
    asm volatile("ldmatrix.sync.aligned.m8n8.x4.shared.b16 {%0,%1,%2,%3}, [%4];"
                 : "=r"(r[0]), "=r"(r[1]), "=r"(r[2]), "=r"(r[3]) : "r"(addr));
}
__device__ __forceinline__ void ldsm_x4t(uint32_t r[4], uint32_t addr) {
    asm volatile("ldmatrix.sync.aligned.m8n8.x4.trans.shared.b16 {%0,%1,%2,%3}, [%4];"
                 : "=r"(r[0]), "=r"(r[1]), "=r"(r[2]), "=r"(r[3]) : "r"(addr));
}
__device__ __forceinline__ void stsm_x4(uint32_t addr, const uint32_t r[4]) {
    asm volatile("stmatrix.sync.aligned.m8n8.x4.shared.b16 [%0], {%1,%2,%3,%4};"
                 :: "r"(addr), "r"(r[0]), "r"(r[1]), "r"(r[2]), "r"(r[3]) : "memory");
}
__device__ __forceinline__ void mma_f16(float d[4], const uint32_t a[4],
                                        uint32_t b0, uint32_t b1) {
    asm volatile("mma.sync.aligned.m16n8k16.row.col.f32.f16.f16.f32 "
                 "{%0,%1,%2,%3}, {%4,%5,%6,%7}, {%8,%9}, {%0,%1,%2,%3};"
                 : "+f"(d[0]), "+f"(d[1]), "+f"(d[2]), "+f"(d[3])
                 : "r"(a[0]), "r"(a[1]), "r"(a[2]), "r"(a[3]), "r"(b0), "r"(b1));
}
// 2-warp pair barrier (warps mb and mb+4), named barrier id = mb+1
#define BARP(id) asm volatile("bar.sync %0, 64;" :: "r"(id) : "memory")

__device__ __forceinline__ uint32_t pack_f16(float y0, float y1) {
    __half2 h = __floats2half2_rn(y0, y1);      // y0 in low half
    return *reinterpret_cast<uint32_t*>(&h);
}

// ---------------- K0: fold BN into weights, emit fp16 images -----------------
__global__ void fold_kernel(const float* __restrict__ W1, const float* __restrict__ W2,
                            const float* __restrict__ W3, const float* __restrict__ Wc1,
                            const float* __restrict__ Wc2,
                            const float* __restrict__ g1, const float* __restrict__ v1,
                            const float* __restrict__ g2, const float* __restrict__ b2,
                            const float* __restrict__ m2, const float* __restrict__ v2,
                            const float* __restrict__ g3, const float* __restrict__ b3,
                            const float* __restrict__ m3, const float* __restrict__ v3,
                            const float* __restrict__ gc1, const float* __restrict__ bc1,
                            const float* __restrict__ mc1, const float* __restrict__ vc1) {
    __shared__ float a2s[H_], a3s[H_], ac1s[H_];
    int tid = threadIdx.x;
    if (tid < H_) {
        float A1 = g1[tid] * rsqrtf(v1[tid] + 1e-5f);
        d_w0[tid] = A1 * W1[tid * (F_ + 1)];
        float A2 = g2[tid] * rsqrtf(v2[tid] + 1e-5f);
        a2s[tid] = A2;  d_b2v[tid] = b2[tid] - A2 * m2[tid];
        float A3 = g3[tid] * rsqrtf(v3[tid] + 1e-5f);
        a3s[tid] = A3;  d_b3v[tid] = b3[tid] - A3 * m3[tid];
        float Ac = gc1[tid] * rsqrtf(vc1[tid] + 1e-5f);
        ac1s[tid] = Ac; d_bc1v[tid] = bc1[tid] - Ac * mc1[tid];
    }
    __syncthreads();
    for (int i = tid; i < 64 * 64; i += 256) {
        int k = i >> 6, g = i & 63;
        float w2v = a2s[g] * W2[g * H_ + k];
        float w3v = a3s[g] * W3[g * H_ + k];
        uint32_t off = (uint32_t)k * 128u + ((((uint32_t)g >> 3) ^ ((uint32_t)k & 7u)) << 4)
                       + (((uint32_t)g & 7u) << 1);
        d_W2img[off >> 1] = __half_as_ushort(__float2half_rn(w2v));
        d_W3img[off >> 1] = __half_as_ushort(__float2half_rn(w3v));
    }
    for (int i = tid; i < H_ * H_; i += 256) {
        int k = i >> 6, g = i & 63;
        d_Wc1t[k * H_ + g] = ac1s[g] * Wc1[g * H_ + k];
    }
    for (int i = tid; i < H_ * O_; i += 256) {
        int h = i >> 7, o = i & 127;
        d_Wc2t[h * O_ + o] = Wc2[o * H_ + h];
    }
}

// ---------------- K1: A' = BN1-folded W1[:,1:] @ t ---------------------------
__global__ void ap_kernel(const float* __restrict__ t, const float* __restrict__ W1,
                          const float* __restrict__ g1, const float* __restrict__ b1,
                          const float* __restrict__ m1, const float* __restrict__ v1) {
    int bh = blockIdx.x;
    int b = bh >> 6, h = bh & 63;
    int m = threadIdx.x;
    __shared__ float w[F_];
    if (m < F_) w[m] = W1[h * (F_ + 1) + 1 + m];
    __syncthreads();
    const float* tp = t + (size_t)b * F_ * M_ + m;
    float acc = 0.f;
#pragma unroll 8
    for (int f = 0; f < F_; f++) acc = fmaf(w[f], tp[f * M_], acc);
    float A1 = g1[h] * rsqrtf(v1[h] + 1e-5f);
    float B1 = b1[h] - A1 * m1[h];
    d_Ap[bh * M_ + m] = fmaf(A1, acc, B1);
}

// ---------------- K2: cosine-similarity GEMM + inline norms ------------------
__global__ void __launch_bounds__(256) cos_kernel(const float* __restrict__ t,
                                                  const float* __restrict__ s) {
    int b = blockIdx.z;
    int m0 = blockIdx.y * 64;
    int n0 = blockIdx.x * 64;
    __shared__ float ts[16][64];
    __shared__ float ss[16][64];
    __shared__ float ntp[4][64], nsp[4][64];
    __shared__ float nts[64], nss[64];
    int tid = threadIdx.x, ty = tid >> 4, tx = tid & 15;
    float acc[4][4] = {};
    float tss = 0.f, sss = 0.f;
    const float* tb = t + (size_t)b * F_ * M_;
    const float* sb = s + (size_t)b * F_ * N_;
    for (int f0 = 0; f0 < F_; f0 += 16) {
        __syncthreads();
#pragma unroll
        for (int i = 0; i < 4; i++) {
            int e = tid + i * 256;
            int fr = e >> 6, cc = e & 63;
            float tv = tb[(f0 + fr) * M_ + m0 + cc];
            float sv = sb[(f0 + fr) * N_ + n0 + cc];
            ts[fr][cc] = tv; tss = fmaf(tv, tv, tss);
            ss[fr][cc] = sv; sss = fmaf(sv, sv, sss);
        }
        __syncthreads();
#pragma unroll
        for (int k = 0; k < 16; k++) {
            float4 av = *(const float4*)&ts[k][4 * ty];
            float4 bv = *(const float4*)&ss[k][4 * tx];
            float a0 = av.x, a1 = av.y, a2 = av.z, a3 = av.w;
            float b0 = bv.x, b1 = bv.y, b2 = bv.z, b3 = bv.w;
            acc[0][0] = fmaf(a0, b0, acc[0][0]); acc[0][1] = fmaf(a0, b1, acc[0][1]);
            acc[0][2] = fmaf(a0, b2, acc[0][2]); acc[0][3] = fmaf(a0, b3, acc[0][3]);
            acc[1][0] = fmaf(a1, b0, acc[1][0]); acc[1][1] = fmaf(a1, b1, acc[1][1]);
            acc[1][2] = fmaf(a1, b2, acc[1][2]); acc[1][3] = fmaf(a1, b3, acc[1][3]);
            acc[2][0] = fmaf(a2, b0, acc[2][0]); acc[2][1] = fmaf(a2, b1, acc[2][1]);
            acc[2][2] = fmaf(a2, b2, acc[2][2]); acc[2][3] = fmaf(a2, b3, acc[2][3]);
            acc[3][0] = fmaf(a3, b0, acc[3][0]); acc[3][1] = fmaf(a3, b1, acc[3][1]);
            acc[3][2] = fmaf(a3, b2, acc[3][2]); acc[3][3] = fmaf(a3, b3, acc[3][3]);
        }
    }
    ntp[tid >> 6][tid & 63] = tss;
    nsp[tid >> 6][tid & 63] = sss;
    __syncthreads();
    if (tid < 64)
        nts[tid] = sqrtf(ntp[0][tid] + ntp[1][tid] + ntp[2][tid] + ntp[3][tid]);
    else if (tid < 128) {
        int c = tid - 64;
        nss[c] = sqrtf(nsp[0][c] + nsp[1][c] + nsp[2][c] + nsp[3][c]);
    }
    __syncthreads();
    float ntv[4], nsv[4];
#pragma unroll
    for (int r = 0; r < 4; r++) ntv[r] = nts[4 * ty + r];
#pragma unroll
    for (int c = 0; c < 4; c++) nsv[c] = nss[4 * tx + c];
#pragma unroll
    for (int c = 0; c < 4; c++) {
        int n = n0 + 4 * tx + c;
        float4 v;
        v.x = acc[0][c] / fmaxf(ntv[0] * nsv[c], 1e-8f);
        v.y = acc[1][c] / fmaxf(ntv[1] * nsv[c], 1e-8f);
        v.z = acc[2][c] / fmaxf(ntv[2] * nsv[c], 1e-8f);
        v.w = acc[3][c] / fmaxf(ntv[3] * nsv[c], 1e-8f);
        *(float4*)&d_cos[((size_t)b * N_ + n) * M_ + m0 + 4 * ty] = v;
    }
}

// ---------------- K3: fused MLP, fragment-direct GEMM1 A ---------------------
// SMEM map (bytes):
//  0       W2 image (8192)
//  8192    W3 image (8192)
//  16384   X2 [128 m][144B] fp16 (18432)
//  34816   aps_f fragment-ordered fp16 [128 glane][72 halves] (18432)
//  53248   red [8 nl][4 mb][64 g] f32 (8192)
//  61440   w0f [32 l][4 kt][2 c8] half2 (1024)
//  62464   b2s (256) | 62720 b3s (256)
#define XS_OFF   16384
#define APF_OFF  34816
#define RED_OFF  53248
#define W0F_OFF  61440
#define B2_OFF   62464
#define B3_OFF   62720
#define MAIN_SMEM_BYTES 62976

// GEMM2: warp (gb,mb) computes [rows mb*32..+31] x [cols gb*32..+31], K=64 fp16
__device__ __forceinline__ void do_gemm(uint32_t xs_u32, uint32_t w_u32,
                                        int lane, int gb, int mb, float acc[2][4][4]) {
    uint32_t aaddr0 = xs_u32 + (uint32_t)((mb * 32 + (lane & 15)) * ROWB + ((lane >> 4) << 4));
    uint32_t aaddr1 = aaddr0 + 16 * ROWB;
    int kk = (lane & 7) + ((lane >> 3) & 1) * 8;
    int nc0 = gb * 4 + (lane >> 4);
    uint32_t baddr0 = w_u32 + (uint32_t)(kk * 128 + ((nc0 ^ (lane & 7)) << 4));
    uint32_t baddr1 = w_u32 + (uint32_t)(kk * 128 + (((nc0 + 2) ^ (lane & 7)) << 4));
#pragma unroll
    for (int k = 0; k < 4; k++) {
        uint32_t a0[4], a1[4], b0[4], b1[4];
        ldsm_x4 (a0, aaddr0 + k * 32);
        ldsm_x4 (a1, aaddr1 + k * 32);
        ldsm_x4t(b0, baddr0 + k * 2048);
        ldsm_x4t(b1, baddr1 + k * 2048);
        mma_f16(acc[0][0], a0, b0[0], b0[1]); mma_f16(acc[0][1], a0, b0[2], b0[3]);
        mma_f16(acc[0][2], a0, b1[0], b1[1]); mma_f16(acc[0][3], a0, b1[2], b1[3]);
        mma_f16(acc[1][0], a1, b0[0], b0[1]); mma_f16(acc[1][1], a1, b0[2], b0[3]);
        mma_f16(acc[1][2], a1, b1[0], b1[1]); mma_f16(acc[1][3], a1, b1[2], b1[3]);
    }
}

__global__ void __launch_bounds__(256, 3) main_kernel(const float* __restrict__ bc2,
                                                      float* __restrict__ out) {
    extern __shared__ char smem[];
    __half* apsh = (__half*)(smem + APF_OFF);   // [glane][72]
    float* red = (float*)(smem + RED_OFF);
    float* b2s = (float*)(smem + B2_OFF);
    float* b3s = (float*)(smem + B3_OFF);

    uint32_t sb32 = smem_to_u32(smem);
    uint32_t xs_u32 = sb32 + XS_OFF;

    int tid = threadIdx.x;
    int wid = tid >> 5, lane = tid & 31;
    int gb = wid >> 2, mb = wid & 3;
    int barid = mb + 1;
    int b = blockIdx.y;
    int n0 = blockIdx.x * NPB;

    // stage weights + biases + w0 frags; init red
    {
        const uint4* sw2 = (const uint4*)d_W2img;
        const uint4* sw3 = (const uint4*)d_W3img;
        uint4* dw2 = (uint4*)smem;
        uint4* dw3 = (uint4*)(smem + 8192);
#pragma unroll
        for (int i = 0; i < 2; i++) {
            dw2[tid + i * 256] = sw2[tid + i * 256];
            dw3[tid + i * 256] = sw3[tid + i * 256];
        }
        if (tid < 64) {
            b2s[tid] = d_b2v[tid];
            b3s[tid] = d_b3v[tid];
        }
        // w0f[l][kt][c8] half2: cols kt*16 + (l&3)*2 + c8*8 + {0,1}
        {
            int l = tid >> 3, kt = (tid >> 1) & 3, c8 = tid & 1;
            int h0 = kt * 16 + (l & 3) * 2 + c8 * 8;
            __half2 w = __halves2half2(__float2half_rn(d_w0[h0]),
                                       __float2half_rn(d_w0[h0 + 1]));
            *(__half2*)(smem + W0F_OFF + tid * 4) = w;
        }
#pragma unroll
        for (int i = 0; i < 8; i++) red[tid + i * 256] = 0.f;
    }
    __syncthreads();

    // hoist w0 fragments into registers: w0h2[kt*2 + c8]
    __half2 w0h2[8];
    {
        const uint4* wf = (const uint4*)(smem + W0F_OFF + lane * 32);
        uint4 wlo = wf[0], whi = wf[1];
        w0h2[0] = *(__half2*)&wlo.x; w0h2[1] = *(__half2*)&wlo.y;
        w0h2[2] = *(__half2*)&wlo.z; w0h2[3] = *(__half2*)&wlo.w;
        w0h2[4] = *(__half2*)&whi.x; w0h2[5] = *(__half2*)&whi.y;
        w0h2[6] = *(__half2*)&whi.z; w0h2[7] = *(__half2*)&whi.w;
    }
    const __half2 zero2 = __floats2half2_rn(0.f, 0.f);

    for (int mt = 0; mt < 2; mt++) {
        __syncthreads();   // all GEMM1 readers of aps_f done
        // stage Ap into fragment-ordered fp16 aps_f:
        // (m,h) -> glane = (m>>5)*32 + (m&7... see mapping below
#pragma unroll
        for (int i = 0; i < 8; i++) {
            int e = tid + i * 256;           // 0..2047
            int h = e >> 5;                  // 0..63
            int mq = e & 31;                 // m quad index
            float4 v = *(const float4*)(d_Ap + ((size_t)b * H_ + h) * M_ + mt * 128 + 4 * mq);
            int kt = h >> 4, c8 = (h >> 3) & 1, par = h & 1, lc = (h >> 1) & 3;
            float vals[4] = {v.x, v.y, v.z, v.w};
#pragma unroll
            for (int j = 0; j < 4; j++) {
                int m = 4 * mq + j;
                int mb2 = m >> 5, rb = m & 31;
                int l = (rb & 7) * 4 + lc;
                int q = rb >> 3;
                int r = kt * 8 + q * 2 + c8;
                apsh[(mb2 * 32 + l) * 72 + r * 2 + par] = __float2half_rn(vals[j]);
            }
        }
        __syncthreads();

        // per-warp invariant addresses
        const uint4* ap4 = (const uint4*)(smem + APF_OFF + (mb * 32 + lane) * 144);
        int kk = (lane & 7) + ((lane >> 3) & 1) * 8;
        int nc0 = gb * 4 + (lane >> 4);
        uint32_t b2addr0 = sb32 + (uint32_t)(kk * 128 + ((nc0 ^ (lane & 7)) << 4));
        uint32_t b2addr1 = sb32 + (uint32_t)(kk * 128 + (((nc0 + 2) ^ (lane & 7)) << 4));
        const float* cosb = d_cos + ((size_t)b * N_ + n0) * M_ + mt * 128 + mb * 32 + (lane >> 2);

        for (int nl = 0; nl < NPB; nl++) {
            // ---- cv broadcast per row-quarter ----
            __half2 cvh2[4];
#pragma unroll
            for (int q = 0; q < 4; q++) {
                float c = __ldg(cosb + nl * M_ + 8 * q);
                cvh2[q] = __half2half2(__float2half_rn(c));
            }

            // ---- GEMM1 with fragment-direct A: relu(w0*cv + ap) in-register ----
            float acc[2][4][4] = {};
#pragma unroll
            for (int kt = 0; kt < 4; kt++) {
                uint4 lo = ap4[kt * 2];
                uint4 hi = ap4[kt * 2 + 1];
                uint32_t u[8] = {lo.x, lo.y, lo.z, lo.w, hi.x, hi.y, hi.z, hi.w};
                uint32_t x[8];
#pragma unroll
                for (int j = 0; j < 8; j++) {
                    __half2 a = __hfma2(w0h2[kt * 2 + (j & 1)], cvh2[j >> 1],
                                        *(__half2*)&u[j]);
                    a = __hmax2(a, zero2);
                    x[j] = *(uint32_t*)&a;
                }
                uint32_t b0[4], b1[4];
                ldsm_x4t(b0, b2addr0 + kt * 2048);
                ldsm_x4t(b1, b2addr1 + kt * 2048);
                uint32_t a0[4] = {x[0], x[2], x[1], x[3]};
                uint32_t a1[4] = {x[4], x[6], x[5], x[7]};
                mma_f16(acc[0][0], a0, b0[0], b0[1]); mma_f16(acc[0][1], a0, b0[2], b0[3]);
                mma_f16(acc[0][2], a0, b1[0], b1[1]); mma_f16(acc[0][3], a0, b1[2], b1[3]);
                mma_f16(acc[1][0], a1, b0[0], b0[1]); mma_f16(acc[1][1], a1, b0[2], b0[3]);
                mma_f16(acc[1][2], a1, b1[0], b1[1]); mma_f16(acc[1][3], a1, b1[2], b1[3]);
            }
            BARP(barid);   // pair's GEMM2 of prev iter done reading X2

            // ---- epilogue 1: relu(+b2), pack fp16, stsm into X2 ----
            {
                int j = lane >> 3, r = lane & 7;
                int g0 = gb * 32 + 2 * (lane & 3);
                uint32_t adbase = xs_u32
                    + (uint32_t)((mb * 32 + (j & 1) * 8 + r) * ROWB + gb * 64 + (j >> 1) * 16);
#pragma unroll
                for (int i = 0; i < 2; i++) {
#pragma unroll
                    for (int tp = 0; tp < 2; tp++) {
                        int t0 = 2 * tp, t1 = t0 + 1;
                        float b00 = b2s[g0 + 8 * t0], b01 = b2s[g0 + 8 * t0 + 1];
                        float b10 = b2s[g0 + 8 * t1], b11 = b2s[g0 + 8 * t1 + 1];
                        uint32_t hh[4];
                        hh[0] = pack_f16(fmaxf(acc[i][t0][0] + b00, 0.f),
                                         fmaxf(acc[i][t0][1] + b01, 0.f));
                        hh[1] = pack_f16(fmaxf(acc[i][t0][2] + b00, 0.f),
                                         fmaxf(acc[i][t0][3] + b01, 0.f));
                        hh[2] = pack_f16(fmaxf(acc[i][t1][0] + b10, 0.f),
                                         fmaxf(acc[i][t1][1] + b11, 0.f));
                        hh[3] = pack_f16(fmaxf(acc[i][t1][2] + b10, 0.f),
                                         fmaxf(acc[i][t1][3] + b11, 0.f));
                        stsm_x4(adbase + (uint32_t)(i * 16 * ROWB + t0 * 16), hh);
                    }
                }
            }
            BARP(barid);   // pair's X2 complete

            // ---- GEMM2: W3f @ X2 ----
            float acc2[2][4][4] = {};
            do_gemm(xs_u32, sb32 + 8192, lane, gb, mb, acc2);

            // ---- epilogue 2: relu(+b3), max over m -> red RMW (race-free) ----
            {
                int g0 = gb * 32 + 2 * (lane & 3);
#pragma unroll
                for (int t = 0; t < 4; t++) {
#pragma unroll
                    for (int d = 0; d < 2; d++) {
                        int gg = g0 + d + 8 * t;
                        float v = fmaxf(fmaxf(acc2[0][t][d], acc2[0][t][2 + d]),
                                        fmaxf(acc2[1][t][d], acc2[1][t][2 + d]));
                        v = fmaxf(v + b3s[gg], 0.f);
                        v = fmaxf(v, __shfl_xor_sync(0xFFFFFFFFu, v, 4));
                        v = fmaxf(v, __shfl_xor_sync(0xFFFFFFFFu, v, 8));
                        v = fmaxf(v, __shfl_xor_sync(0xFFFFFFFFu, v, 16));
                        if (lane < 4) {
                            int ri = nl * 256 + mb * 64 + gg;
                            red[ri] = fmaxf(red[ri], v);
                        }
                    }
                }
            }
            // no barrier: next GEMM1 touches only aps_f (read-only) and regs.
        }
    }

    // ---- fused head: pool -> c = relu(Wc1f p + bc1) -> out = Wc2 c + bc2 ----
    __syncthreads();
    float* ps = (float*)(smem + APF_OFF);   // reuse (512 floats)
    float* cs = (float*)(smem + XS_OFF);    // reuse (512 floats)
#pragma unroll
    for (int i = 0; i < 2; i++) {
        int e = tid + i * 256;
        int nl = e >> 6, h = e & 63;
        const float* r = red + nl * 256;
        ps[e] = fmaxf(fmaxf(r[h], r[64 + h]), fmaxf(r[128 + h], r[192 + h]));
    }
    __syncthreads();
#pragma unroll
    for (int i = 0; i < 2; i++) {
        int e = tid + i * 256;
        int nl = e >> 6, g = e & 63;
        float acc = d_bc1v[g];
        const float* pv = ps + nl * 64;
#pragma unroll 16
        for (int h = 0; h < 64; h++) acc = fmaf(__ldg(d_Wc1t + h * 64 + g), pv[h], acc);
        cs[e] = fmaxf(acc, 0.f);
    }
    __syncthreads();
#pragma unroll
    for (int i = 0; i < 4; i++) {
        int e = tid + i * 256;
        int nl = e >> 7, o = e & 127;
        float acc = __ldg(bc2 + o);
        const float* cv = cs + nl * 64;
#pragma unroll 16
        for (int h = 0; h < 64; h++) acc = fmaf(__ldg(d_Wc2t + h * 128 + o), cv[h], acc);
        out[((size_t)b * O_ + o) * N_ + n0 + nl] = acc;
    }
}

// ---------------- launch ------------------------------------------------------
extern "C" void kernel_launch(void* const* d_in, const int* in_sizes, int n_in,
                              void* d_out, int out_size) {
    const float* t   = (const float*)d_in[0];
    const float* s   = (const float*)d_in[1];
    const float* W1  = (const float*)d_in[2];
    const float* W2  = (const float*)d_in[3];
    const float* W3  = (const float*)d_in[4];
    const float* Wc1 = (const float*)d_in[5];
    const float* Wc2 = (const float*)d_in[6];
    const float* bc2 = (const float*)d_in[7];
    const float* g1 = (const float*)d_in[8],  *b1 = (const float*)d_in[9];
    const float* m1 = (const float*)d_in[10], *v1 = (const float*)d_in[11];
    const float* g2 = (const float*)d_in[12], *b2 = (const float*)d_in[13];
    const float* m2 = (const float*)d_in[14], *v2 = (const float*)d_in[15];
    const float* g3 = (const float*)d_in[16], *b3 = (const float*)d_in[17];
    const float* m3 = (const float*)d_in[18], *v3 = (const float*)d_in[19];
    const float* gc1 = (const float*)d_in[20], *bc1 = (const float*)d_in[21];
    const float* mc1 = (const float*)d_in[22], *vc1 = (const float*)d_in[23];
    float* out = (float*)d_out;

    cudaFuncSetAttribute(main_kernel, cudaFuncAttributeMaxDynamicSharedMemorySize,
                         MAIN_SMEM_BYTES);

    fold_kernel<<<1, 256>>>(W1, W2, W3, Wc1, Wc2, g1, v1,
                            g2, b2, m2, v2, g3, b3, m3, v3, gc1, bc1, mc1, vc1);
    ap_kernel<<<B_ * H_, 256>>>(t, W1, g1, b1, m1, v1);
    cos_kernel<<<dim3(N_ / 64, M_ / 64, B_), 256>>>(t, s);
    main_kernel<<<dim3(N_ / NPB, B_), 256, MAIN_SMEM_BYTES>>>(bc2, out);
}